// round 2
// baseline (speedup 1.0000x reference)
#include <cuda_runtime.h>
#include <cuda_bf16.h>
#include <math.h>

// Problem constants
#define Bsz 2
#define SEQ 2048
#define HID 1024
#define NHEAD 16
#define HDIM 64
#define SCALE 0.125f      // 64^-0.5
#define EPS 1e-6f

#define MTOT (Bsz*SEQ)    // 4096

// Scratch (device globals: allocation-free)
__device__ float g_Q[MTOT * HID];
__device__ float g_K[MTOT * HID];
__device__ float g_V[MTOT * HID];
__device__ float g_A[MTOT * HID];

// ---------------------------------------------------------------------------
// GEMM: C[M,N] = A[M,K] * B[N,K]^T   (both row-major, K contiguous)
// 128x128 tile, BK=16, 256 threads, 8x8 per thread.
// ---------------------------------------------------------------------------
__global__ __launch_bounds__(256) void gemm_nt_kernel(
    const float* __restrict__ A, const float* __restrict__ B,
    float* __restrict__ C, int M, int N, int K)
{
    __shared__ float As[16][132];
    __shared__ float Bs[16][132];

    const int tid = threadIdx.x;
    const int tn8 = tid & 15;        // 0..15 -> col group
    const int tm8 = tid >> 4;        // 0..15 -> row group
    const int mBase = blockIdx.y * 128;
    const int nBase = blockIdx.x * 128;

    float acc[8][8];
#pragma unroll
    for (int i = 0; i < 8; ++i)
#pragma unroll
        for (int j = 0; j < 8; ++j) acc[i][j] = 0.f;

    for (int kBase = 0; kBase < K; kBase += 16) {
        // load A tile (128x16) and B tile (128x16), transposed into smem
#pragma unroll
        for (int it = 0; it < 2; ++it) {
            int slot = tid + it * 256;       // 0..511 float4 slots
            int row = slot >> 2;             // 0..127
            int c4  = slot & 3;              // 0..3
            float4 av = *(const float4*)(&A[(mBase + row) * K + kBase + c4 * 4]);
            As[c4*4+0][row] = av.x;
            As[c4*4+1][row] = av.y;
            As[c4*4+2][row] = av.z;
            As[c4*4+3][row] = av.w;
            float4 bv = *(const float4*)(&B[(nBase + row) * K + kBase + c4 * 4]);
            Bs[c4*4+0][row] = bv.x;
            Bs[c4*4+1][row] = bv.y;
            Bs[c4*4+2][row] = bv.z;
            Bs[c4*4+3][row] = bv.w;
        }
        __syncthreads();

#pragma unroll
        for (int k = 0; k < 16; ++k) {
            float a[8], b[8];
#pragma unroll
            for (int i = 0; i < 8; ++i) a[i] = As[k][tm8 * 8 + i];
#pragma unroll
            for (int j = 0; j < 8; ++j) b[j] = Bs[k][tn8 * 8 + j];
#pragma unroll
            for (int i = 0; i < 8; ++i)
#pragma unroll
                for (int j = 0; j < 8; ++j)
                    acc[i][j] = fmaf(a[i], b[j], acc[i][j]);
        }
        __syncthreads();
    }

    // write back
#pragma unroll
    for (int i = 0; i < 8; ++i) {
        int row = mBase + tm8 * 8 + i;
        float* cp = &C[row * N + nBase + tn8 * 8];
#pragma unroll
        for (int j4 = 0; j4 < 2; ++j4) {
            float4 v;
            v.x = acc[i][j4*4+0]; v.y = acc[i][j4*4+1];
            v.z = acc[i][j4*4+2]; v.w = acc[i][j4*4+3];
            *(float4*)(cp + j4 * 4) = v;
        }
    }
}

// ---------------------------------------------------------------------------
// Sigmoid attention, flash style.
// grid: (S/64, NHEAD, Bsz). 256 threads.
// Per CTA: 64 queries of one (b,h). Loop over 32 key tiles of 64.
//   S = Q K^T, P = sigmoid(S*scale)  (P overwrites K smem buffer)
//   O += P V, denom += rowsum(P)
// Final: O / (denom + eps) -> g_A in [B*S, HID] layout (head cols h*64..)
// ---------------------------------------------------------------------------
__global__ __launch_bounds__(256) void attn_kernel()
{
    __shared__ float Qs[64][64];   // [query][dim]
    __shared__ float Ks[64][64];   // [dim][key]  (K transposed); reused as P [query][key]
    __shared__ float Vs[64][64];   // [key][dim]

    const int tid = threadIdx.x;
    const int tx = tid & 15;       // col group (keys / dims)
    const int ty = tid >> 4;       // row group (queries)
    const int qt = blockIdx.x;
    const int h  = blockIdx.y;
    const int b  = blockIdx.z;

    const float* Qg = g_Q + (size_t)b * SEQ * HID + h * HDIM;
    const float* Kg = g_K + (size_t)b * SEQ * HID + h * HDIM;
    const float* Vg = g_V + (size_t)b * SEQ * HID + h * HDIM;

    // load Q tile: 64 rows x 64 dims
    for (int i = tid; i < 64 * 16; i += 256) {
        int r = i >> 4, c4 = i & 15;
        float4 v = *(const float4*)(&Qg[(qt * 64 + r) * HID + c4 * 4]);
        *(float4*)&Qs[r][c4 * 4] = v;
    }

    float o[4][4];
#pragma unroll
    for (int i = 0; i < 4; ++i)
#pragma unroll
        for (int j = 0; j < 4; ++j) o[i][j] = 0.f;
    float denom = 0.f;   // valid for tid < 64: row `tid`

    for (int kt = 0; kt < SEQ / 64; ++kt) {
        __syncthreads();   // protect Ks/Vs reuse from previous iteration
        // load K tile transposed (Ks[d][key]) and V tile (Vs[key][d])
        for (int i = tid; i < 64 * 16; i += 256) {
            int r = i >> 4, c4 = i & 15;
            float4 kv = *(const float4*)(&Kg[(kt * 64 + r) * HID + c4 * 4]);
            Ks[c4*4+0][r] = kv.x;
            Ks[c4*4+1][r] = kv.y;
            Ks[c4*4+2][r] = kv.z;
            Ks[c4*4+3][r] = kv.w;
            float4 vv = *(const float4*)(&Vg[(kt * 64 + r) * HID + c4 * 4]);
            *(float4*)&Vs[r][c4 * 4] = vv;
        }
        __syncthreads();

        // S = Q K^T (registers)
        float acc[4][4];
#pragma unroll
        for (int i = 0; i < 4; ++i)
#pragma unroll
            for (int j = 0; j < 4; ++j) acc[i][j] = 0.f;
#pragma unroll 4
        for (int k = 0; k < 64; ++k) {
            float a[4], bb[4];
#pragma unroll
            for (int i = 0; i < 4; ++i) a[i] = Qs[ty * 4 + i][k];
#pragma unroll
            for (int j = 0; j < 4; ++j) bb[j] = Ks[k][tx * 4 + j];
#pragma unroll
            for (int i = 0; i < 4; ++i)
#pragma unroll
                for (int j = 0; j < 4; ++j)
                    acc[i][j] = fmaf(a[i], bb[j], acc[i][j]);
        }
        __syncthreads();   // everyone done reading Ks (K data)

        // P = sigmoid(scale * S) -> into Ks buffer as [query][key]
#pragma unroll
        for (int i = 0; i < 4; ++i)
#pragma unroll
            for (int j = 0; j < 4; ++j)
                Ks[ty * 4 + i][tx * 4 + j] =
                    1.f / (1.f + expf(-SCALE * acc[i][j]));
        __syncthreads();

        // row sums of P (threads 0..63 own one row each)
        if (tid < 64) {
            float s = 0.f;
#pragma unroll 8
            for (int j = 0; j < 64; ++j) s += Ks[tid][j];
            denom += s;
        }

        // O += P V
#pragma unroll 4
        for (int k = 0; k < 64; ++k) {
            float a[4], bb[4];
#pragma unroll
            for (int i = 0; i < 4; ++i) a[i] = Ks[ty * 4 + i][k];
#pragma unroll
            for (int j = 0; j < 4; ++j) bb[j] = Vs[k][tx * 4 + j];
#pragma unroll
            for (int i = 0; i < 4; ++i)
#pragma unroll
                for (int j = 0; j < 4; ++j)
                    o[i][j] = fmaf(a[i], bb[j], o[i][j]);
        }
    }

    // broadcast denominators via smem (reuse Vs)
    __syncthreads();
    if (tid < 64) Vs[0][tid] = denom;
    __syncthreads();

    float* Ag = g_A + (size_t)b * SEQ * HID + h * HDIM;
#pragma unroll
    for (int i = 0; i < 4; ++i) {
        int r = ty * 4 + i;
        float inv = 1.f / (Vs[0][r] + EPS);
        float4 v;
        v.x = o[i][0] * inv; v.y = o[i][1] * inv;
        v.z = o[i][2] * inv; v.w = o[i][3] * inv;
        *(float4*)(&Ag[(qt * 64 + r) * HID + tx * 4]) = v;
    }
}

// ---------------------------------------------------------------------------
extern "C" void kernel_launch(void* const* d_in, const int* in_sizes, int n_in,
                              void* d_out, int out_size)
{
    // Non-stream symbol queries first; capture region below is launches only.
    float *Qp, *Kp, *Vp, *Ap;
    cudaGetSymbolAddress((void**)&Qp, g_Q);
    cudaGetSymbolAddress((void**)&Kp, g_K);
    cudaGetSymbolAddress((void**)&Vp, g_V);
    cudaGetSymbolAddress((void**)&Ap, g_A);

    const float* x  = (const float*)d_in[0];
    const float* Wq = (const float*)d_in[1];
    const float* Wk = (const float*)d_in[2];
    const float* Wv = (const float*)d_in[3];
    const float* Wo = (const float*)d_in[4];
    float* out = (float*)d_out;

    dim3 gemmGrid(HID / 128, MTOT / 128);  // (8, 32)
    gemm_nt_kernel<<<gemmGrid, 256>>>(x, Wq, Qp, MTOT, HID, HID);
    gemm_nt_kernel<<<gemmGrid, 256>>>(x, Wk, Kp, MTOT, HID, HID);
    gemm_nt_kernel<<<gemmGrid, 256>>>(x, Wv, Vp, MTOT, HID, HID);

    dim3 attnGrid(SEQ / 64, NHEAD, Bsz);   // (32, 16, 2)
    attn_kernel<<<attnGrid, 256>>>();

    gemm_nt_kernel<<<gemmGrid, 256>>>(Ap, Wo, out, MTOT, HID, HID);
}

// round 3
// speedup vs baseline: 2.4351x; 2.4351x over previous
#include <cuda_runtime.h>
#include <stdint.h>
#include <math.h>

#define Bsz 2
#define SEQ 2048
#define HID 1024
#define NHEAD 16
#define HDIM 64
#define SCALE 0.125f
#define EPS 1e-6f
#define MTOT (Bsz*SEQ)   // 4096

// Scratch (device globals: allocation-free)
__device__ float g_Q[MTOT * HID];
__device__ float g_K[MTOT * HID];
__device__ float g_V[MTOT * HID];
__device__ float g_A[MTOT * HID];

// ---------------------------------------------------------------------------
// Helpers
// ---------------------------------------------------------------------------
__device__ __forceinline__ float f2tf32(float x) {
    uint32_t u;
    asm("cvt.rna.tf32.f32 %0, %1;" : "=r"(u) : "f"(x));
    return __uint_as_float(u);
}

__device__ __forceinline__ void mma_tf32(float* d, const uint32_t* a, const uint32_t* b) {
    asm volatile(
        "mma.sync.aligned.m16n8k8.row.col.f32.tf32.tf32.f32 "
        "{%0,%1,%2,%3},{%4,%5,%6,%7},{%8,%9},{%0,%1,%2,%3};\n"
        : "+f"(d[0]), "+f"(d[1]), "+f"(d[2]), "+f"(d[3])
        : "r"(a[0]), "r"(a[1]), "r"(a[2]), "r"(a[3]), "r"(b[0]), "r"(b[1]));
}

__device__ __forceinline__ uint32_t fbits(float x) { return __float_as_uint(x); }

// ---------------------------------------------------------------------------
// TF32 GEMM: C[M,N] = A[M,K] * B[N,K]^T  (row-major, K contiguous both)
// CTA tile 128x128, BK=32, 8 warps, warp tile 32x64 (2 m-frags x 8 n-frags).
// Register-prefetch pipeline over 32 k-tiles.
// ---------------------------------------------------------------------------
#define GS 36  // smem row stride (floats): 144B, 16B-aligned, conflict-free frags

__global__ __launch_bounds__(256) void gemm_tf32(
    const float* __restrict__ A, const float* __restrict__ B,
    float* __restrict__ C, int M, int N, int K)
{
    __shared__ float As[128 * GS];
    __shared__ float Bs[128 * GS];

    const int tid  = threadIdx.x;
    const int lane = tid & 31;
    const int warp = tid >> 5;
    const int g    = lane >> 2;      // 0..7
    const int tk   = lane & 3;       // 0..3
    const int wm   = (warp & 3) * 32;
    const int wn   = (warp >> 2) * 64;
    const int mBase = blockIdx.y * 128;
    const int nBase = blockIdx.x * 128;

    float acc[2][8][4];
#pragma unroll
    for (int mf = 0; mf < 2; ++mf)
#pragma unroll
        for (int nf = 0; nf < 8; ++nf)
#pragma unroll
            for (int i = 0; i < 4; ++i) acc[mf][nf][i] = 0.f;

    const int T = K / 32;
    float4 fa[4], fb[4];

    // prologue: load k-tile 0
#pragma unroll
    for (int i = 0; i < 4; ++i) {
        int s = tid + 256 * i, r = s >> 3, c = (s & 7) * 4;
        fa[i] = *(const float4*)&A[(size_t)(mBase + r) * K + c];
        fb[i] = *(const float4*)&B[(size_t)(nBase + r) * K + c];
    }

    for (int t = 0; t < T; ++t) {
        __syncthreads();
        // store (with tf32 rounding) to smem
#pragma unroll
        for (int i = 0; i < 4; ++i) {
            int s = tid + 256 * i, r = s >> 3, c = (s & 7) * 4;
            float4 va = fa[i], vb = fb[i];
            va.x = f2tf32(va.x); va.y = f2tf32(va.y);
            va.z = f2tf32(va.z); va.w = f2tf32(va.w);
            vb.x = f2tf32(vb.x); vb.y = f2tf32(vb.y);
            vb.z = f2tf32(vb.z); vb.w = f2tf32(vb.w);
            *(float4*)&As[r * GS + c] = va;
            *(float4*)&Bs[r * GS + c] = vb;
        }
        __syncthreads();
        // prefetch next k-tile into registers
        if (t + 1 < T) {
            int kOff = (t + 1) * 32;
#pragma unroll
            for (int i = 0; i < 4; ++i) {
                int s = tid + 256 * i, r = s >> 3, c = (s & 7) * 4;
                fa[i] = *(const float4*)&A[(size_t)(mBase + r) * K + kOff + c];
                fb[i] = *(const float4*)&B[(size_t)(nBase + r) * K + kOff + c];
            }
        }
        // compute 4 k-steps of 8
#pragma unroll
        for (int ks = 0; ks < 4; ++ks) {
            int k0 = ks * 8;
            uint32_t av[2][4];
#pragma unroll
            for (int mf = 0; mf < 2; ++mf) {
                int r0 = wm + mf * 16 + g;
                av[mf][0] = fbits(As[r0 * GS + k0 + tk]);
                av[mf][1] = fbits(As[(r0 + 8) * GS + k0 + tk]);
                av[mf][2] = fbits(As[r0 * GS + k0 + tk + 4]);
                av[mf][3] = fbits(As[(r0 + 8) * GS + k0 + tk + 4]);
            }
            uint32_t bv[8][2];
#pragma unroll
            for (int nf = 0; nf < 8; ++nf) {
                int rn = wn + nf * 8 + g;
                bv[nf][0] = fbits(Bs[rn * GS + k0 + tk]);
                bv[nf][1] = fbits(Bs[rn * GS + k0 + tk + 4]);
            }
#pragma unroll
            for (int mf = 0; mf < 2; ++mf)
#pragma unroll
                for (int nf = 0; nf < 8; ++nf)
                    mma_tf32(acc[mf][nf], av[mf], bv[nf]);
        }
    }

    // epilogue
#pragma unroll
    for (int mf = 0; mf < 2; ++mf) {
        int r0 = mBase + wm + mf * 16 + g;
#pragma unroll
        for (int nf = 0; nf < 8; ++nf) {
            int c0 = nBase + wn + nf * 8 + 2 * tk;
            float2 v0 = make_float2(acc[mf][nf][0], acc[mf][nf][1]);
            float2 v1 = make_float2(acc[mf][nf][2], acc[mf][nf][3]);
            *(float2*)&C[(size_t)r0 * N + c0]       = v0;
            *(float2*)&C[(size_t)(r0 + 8) * N + c0] = v1;
        }
    }
}

// ---------------------------------------------------------------------------
// TF32 sigmoid attention.
// CTA: 128 queries of one (b,h); loop 64 key-tiles of 32. 8 warps.
//   S warp grid 4q x 2key (warp 32x16), PV/O warp grid 4q x 2d (warp 32x32).
// Q fragments live in registers for the whole kernel.
// smem: Ps 128x36 | Ks 32x68 | Vs 32x68 (Q staged over the union at start).
// ---------------------------------------------------------------------------
#define SM_FLOATS 8960
#define PS_OFF 0
#define KS_OFF 4608
#define VS_OFF 6784

__global__ __launch_bounds__(256) void attn_tf32()
{
    __shared__ float sm[SM_FLOATS];
    float* Ps = sm + PS_OFF;   // stride 36
    float* Ks = sm + KS_OFF;   // stride 68
    float* Vs = sm + VS_OFF;   // stride 68

    const int tid  = threadIdx.x;
    const int lane = tid & 31;
    const int warp = tid >> 5;
    const int g    = lane >> 2;
    const int tk   = lane & 3;
    const int wm   = (warp & 3) * 32;  // q rows (S and O share this)
    const int wn2  = warp >> 2;        // 0/1: key group (*16) for S, d group (*32) for O

    const int qt = blockIdx.x, h = blockIdx.y, b = blockIdx.z;
    const float* Qg = g_Q + ((size_t)b * SEQ + qt * 128) * HID + h * HDIM;
    const float* Kg = g_K + (size_t)b * SEQ * HID + h * HDIM;
    const float* Vg = g_V + (size_t)b * SEQ * HID + h * HDIM;

    // ---- stage Q (128x64) into smem (stride 68), tf32-rounded ----
#pragma unroll
    for (int i = 0; i < 8; ++i) {
        int s = tid + 256 * i, r = s >> 4, c = (s & 15) * 4;
        float4 v = *(const float4*)&Qg[(size_t)r * HID + c];
        v.x = f2tf32(v.x); v.y = f2tf32(v.y); v.z = f2tf32(v.z); v.w = f2tf32(v.w);
        *(float4*)&sm[r * 68 + c] = v;
    }
    __syncthreads();

    // ---- load Q fragments to registers: [kstep][mfrag][4] ----
    uint32_t qa[8][2][4];
#pragma unroll
    for (int ks = 0; ks < 8; ++ks)
#pragma unroll
        for (int mf = 0; mf < 2; ++mf) {
            int r0 = wm + mf * 16 + g;
            qa[ks][mf][0] = fbits(sm[r0 * 68 + ks * 8 + tk]);
            qa[ks][mf][1] = fbits(sm[(r0 + 8) * 68 + ks * 8 + tk]);
            qa[ks][mf][2] = fbits(sm[r0 * 68 + ks * 8 + tk + 4]);
            qa[ks][mf][3] = fbits(sm[(r0 + 8) * 68 + ks * 8 + tk + 4]);
        }

    float oacc[2][4][4];
#pragma unroll
    for (int mf = 0; mf < 2; ++mf)
#pragma unroll
        for (int nf = 0; nf < 4; ++nf)
#pragma unroll
            for (int i = 0; i < 4; ++i) oacc[mf][nf][i] = 0.f;
    float dpart[2][2] = {{0.f, 0.f}, {0.f, 0.f}};  // [mf][row g / g+8]

    // prologue K/V tile 0 (32x64 each); 2 float4 per thread per tensor
    float4 kf[2], vf[2];
#pragma unroll
    for (int i = 0; i < 2; ++i) {
        int s = tid + 256 * i, r = s >> 4, c = (s & 15) * 4;
        kf[i] = *(const float4*)&Kg[(size_t)r * HID + c];
        vf[i] = *(const float4*)&Vg[(size_t)r * HID + c];
    }

    for (int kt = 0; kt < SEQ / 32; ++kt) {
        __syncthreads();  // prev PV done; Qstage consumed (first iter)
#pragma unroll
        for (int i = 0; i < 2; ++i) {
            int s = tid + 256 * i, r = s >> 4, c = (s & 15) * 4;
            float4 k4 = kf[i], v4 = vf[i];
            k4.x = f2tf32(k4.x); k4.y = f2tf32(k4.y); k4.z = f2tf32(k4.z); k4.w = f2tf32(k4.w);
            v4.x = f2tf32(v4.x); v4.y = f2tf32(v4.y); v4.z = f2tf32(v4.z); v4.w = f2tf32(v4.w);
            *(float4*)&Ks[r * 68 + c] = k4;
            *(float4*)&Vs[r * 68 + c] = v4;
        }
        __syncthreads();
        if (kt + 1 < SEQ / 32) {
            const float* Kn = Kg + (size_t)(kt + 1) * 32 * HID;
            const float* Vn = Vg + (size_t)(kt + 1) * 32 * HID;
#pragma unroll
            for (int i = 0; i < 2; ++i) {
                int s = tid + 256 * i, r = s >> 4, c = (s & 15) * 4;
                kf[i] = *(const float4*)&Kn[(size_t)r * HID + c];
                vf[i] = *(const float4*)&Vn[(size_t)r * HID + c];
            }
        }

        // ---- S = Q K^T  (warp: 32q x 16key) ----
        float sacc[2][2][4];
#pragma unroll
        for (int mf = 0; mf < 2; ++mf)
#pragma unroll
            for (int nf = 0; nf < 2; ++nf)
#pragma unroll
                for (int i = 0; i < 4; ++i) sacc[mf][nf][i] = 0.f;
#pragma unroll
        for (int ks = 0; ks < 8; ++ks) {
            uint32_t bv[2][2];
#pragma unroll
            for (int nf = 0; nf < 2; ++nf) {
                int rn = wn2 * 16 + nf * 8 + g;
                bv[nf][0] = fbits(Ks[rn * 68 + ks * 8 + tk]);
                bv[nf][1] = fbits(Ks[rn * 68 + ks * 8 + tk + 4]);
            }
#pragma unroll
            for (int mf = 0; mf < 2; ++mf)
#pragma unroll
                for (int nf = 0; nf < 2; ++nf)
                    mma_tf32(sacc[mf][nf], qa[ks][mf], bv[nf]);
        }

        // ---- P = sigmoid(scale*S), tf32-round, store + row partials ----
#pragma unroll
        for (int mf = 0; mf < 2; ++mf) {
            int r0 = wm + mf * 16 + g;
#pragma unroll
            for (int nf = 0; nf < 2; ++nf) {
                int c0 = wn2 * 16 + nf * 8 + 2 * tk;
                float p00 = f2tf32(1.f / (1.f + __expf(-SCALE * sacc[mf][nf][0])));
                float p01 = f2tf32(1.f / (1.f + __expf(-SCALE * sacc[mf][nf][1])));
                float p10 = f2tf32(1.f / (1.f + __expf(-SCALE * sacc[mf][nf][2])));
                float p11 = f2tf32(1.f / (1.f + __expf(-SCALE * sacc[mf][nf][3])));
                dpart[mf][0] += p00 + p01;
                dpart[mf][1] += p10 + p11;
                *(float2*)&Ps[r0 * 36 + c0]       = make_float2(p00, p01);
                *(float2*)&Ps[(r0 + 8) * 36 + c0] = make_float2(p10, p11);
            }
        }
        __syncthreads();

        // ---- O += P V  (warp: 32q x 32d) ----
#pragma unroll
        for (int ks = 0; ks < 4; ++ks) {
            uint32_t pa[2][4];
#pragma unroll
            for (int mf = 0; mf < 2; ++mf) {
                int r0 = wm + mf * 16 + g;
                pa[mf][0] = fbits(Ps[r0 * 36 + ks * 8 + tk]);
                pa[mf][1] = fbits(Ps[(r0 + 8) * 36 + ks * 8 + tk]);
                pa[mf][2] = fbits(Ps[r0 * 36 + ks * 8 + tk + 4]);
                pa[mf][3] = fbits(Ps[(r0 + 8) * 36 + ks * 8 + tk + 4]);
            }
            uint32_t vb[4][2];
#pragma unroll
            for (int nf = 0; nf < 4; ++nf) {
                int cn = wn2 * 32 + nf * 8 + g;
                vb[nf][0] = fbits(Vs[(ks * 8 + tk) * 68 + cn]);
                vb[nf][1] = fbits(Vs[(ks * 8 + tk + 4) * 68 + cn]);
            }
#pragma unroll
            for (int mf = 0; mf < 2; ++mf)
#pragma unroll
                for (int nf = 0; nf < 4; ++nf)
                    mma_tf32(oacc[mf][nf], pa[mf], vb[nf]);
        }
    }

    // ---- deterministic denominator reduction ----
    __syncthreads();
    float* dp = sm + KS_OFF;  // [128][8]
#pragma unroll
    for (int mf = 0; mf < 2; ++mf) {
        dp[(wm + mf * 16 + g) * 8 + wn2 * 4 + tk]     = dpart[mf][0];
        dp[(wm + mf * 16 + g + 8) * 8 + wn2 * 4 + tk] = dpart[mf][1];
    }
    __syncthreads();

    // ---- epilogue: O / (denom + eps) -> g_A ----
    float* Ag = g_A + ((size_t)b * SEQ + qt * 128) * HID + h * HDIM;
#pragma unroll
    for (int mf = 0; mf < 2; ++mf) {
#pragma unroll
        for (int rr = 0; rr < 2; ++rr) {
            int row = wm + mf * 16 + g + rr * 8;
            float dsum = 0.f;
#pragma unroll
            for (int j = 0; j < 8; ++j) dsum += dp[row * 8 + j];
            float inv = 1.f / (dsum + EPS);
#pragma unroll
            for (int nf = 0; nf < 4; ++nf) {
                int c0 = wn2 * 32 + nf * 8 + 2 * tk;
                float2 v = make_float2(oacc[mf][nf][rr * 2] * inv,
                                       oacc[mf][nf][rr * 2 + 1] * inv);
                *(float2*)&Ag[(size_t)row * HID + c0] = v;
            }
        }
    }
}

// ---------------------------------------------------------------------------
extern "C" void kernel_launch(void* const* d_in, const int* in_sizes, int n_in,
                              void* d_out, int out_size)
{
    float *Qp, *Kp, *Vp, *Ap;
    cudaGetSymbolAddress((void**)&Qp, g_Q);
    cudaGetSymbolAddress((void**)&Kp, g_K);
    cudaGetSymbolAddress((void**)&Vp, g_V);
    cudaGetSymbolAddress((void**)&Ap, g_A);

    const float* x  = (const float*)d_in[0];
    const float* Wq = (const float*)d_in[1];
    const float* Wk = (const float*)d_in[2];
    const float* Wv = (const float*)d_in[3];
    const float* Wo = (const float*)d_in[4];
    float* out = (float*)d_out;

    dim3 gemmGrid(HID / 128, MTOT / 128);  // (8, 32)
    gemm_tf32<<<gemmGrid, 256>>>(x, Wq, Qp, MTOT, HID, HID);
    gemm_tf32<<<gemmGrid, 256>>>(x, Wk, Kp, MTOT, HID, HID);
    gemm_tf32<<<gemmGrid, 256>>>(x, Wv, Vp, MTOT, HID, HID);

    dim3 attnGrid(SEQ / 128, NHEAD, Bsz);  // (16, 16, 2)
    attn_tf32<<<attnGrid, 256>>>();

    gemm_tf32<<<gemmGrid, 256>>>(Ap, Wo, out, MTOT, HID, HID);
}

// round 5
// speedup vs baseline: 2.5067x; 1.0294x over previous
#include <cuda_runtime.h>
#include <stdint.h>
#include <math.h>

#define Bsz 2
#define SEQ 2048
#define HID 1024
#define NHEAD 16
#define HDIM 64
#define SCALE 0.125f
#define EPS 1e-6f
#define MTOT (Bsz*SEQ)   // 4096

// Scratch (device globals: allocation-free)
__device__ float g_Q[MTOT * HID];
__device__ float g_K[MTOT * HID];
__device__ float g_V[MTOT * HID];
__device__ float g_A[MTOT * HID];

// ---------------------------------------------------------------------------
// Helpers
// ---------------------------------------------------------------------------
__device__ __forceinline__ float f2tf32(float x) {
    uint32_t u;
    asm("cvt.rna.tf32.f32 %0, %1;" : "=r"(u) : "f"(x));
    return __uint_as_float(u);
}

__device__ __forceinline__ void mma_tf32(float* d, const uint32_t* a, const uint32_t* b) {
    asm volatile(
        "mma.sync.aligned.m16n8k8.row.col.f32.tf32.tf32.f32 "
        "{%0,%1,%2,%3},{%4,%5,%6,%7},{%8,%9},{%0,%1,%2,%3};\n"
        : "+f"(d[0]), "+f"(d[1]), "+f"(d[2]), "+f"(d[3])
        : "r"(a[0]), "r"(a[1]), "r"(a[2]), "r"(a[3]), "r"(b[0]), "r"(b[1]));
}

__device__ __forceinline__ uint32_t fbits(float x) { return __float_as_uint(x); }

__device__ __forceinline__ void cp16(float* smem_dst, const float* gmem_src) {
    uint32_t s = (uint32_t)__cvta_generic_to_shared(smem_dst);
    asm volatile("cp.async.cg.shared.global [%0], [%1], 16;\n" :: "r"(s), "l"(gmem_src));
}

// ---------------------------------------------------------------------------
// TF32 GEMM: C[M,N] = A[M,K] * B[N,K]^T  (row-major, K contiguous both)
// CTA tile 128x128, BK=32, 8 warps, warp tile 32x64. Register-prefetch.
// ROUND: round outputs to tf32 (for Q/K/V, consumed by tf32 attention).
// ---------------------------------------------------------------------------
#define GS 36

template<bool ROUND>
__global__ __launch_bounds__(256) void gemm_tf32(
    const float* __restrict__ A, const float* __restrict__ B,
    float* __restrict__ C, int M, int N, int K)
{
    __shared__ float As[128 * GS];
    __shared__ float Bs[128 * GS];

    const int tid  = threadIdx.x;
    const int lane = tid & 31;
    const int warp = tid >> 5;
    const int g    = lane >> 2;
    const int tk   = lane & 3;
    const int wm   = (warp & 3) * 32;
    const int wn   = (warp >> 2) * 64;
    const int mBase = blockIdx.y * 128;
    const int nBase = blockIdx.x * 128;

    float acc[2][8][4];
#pragma unroll
    for (int mf = 0; mf < 2; ++mf)
#pragma unroll
        for (int nf = 0; nf < 8; ++nf)
#pragma unroll
            for (int i = 0; i < 4; ++i) acc[mf][nf][i] = 0.f;

    const int T = K / 32;
    float4 fa[4], fb[4];

#pragma unroll
    for (int i = 0; i < 4; ++i) {
        int s = tid + 256 * i, r = s >> 3, c = (s & 7) * 4;
        fa[i] = *(const float4*)&A[(size_t)(mBase + r) * K + c];
        fb[i] = *(const float4*)&B[(size_t)(nBase + r) * K + c];
    }

    for (int t = 0; t < T; ++t) {
        __syncthreads();
#pragma unroll
        for (int i = 0; i < 4; ++i) {
            int s = tid + 256 * i, r = s >> 3, c = (s & 7) * 4;
            float4 va = fa[i], vb = fb[i];
            va.x = f2tf32(va.x); va.y = f2tf32(va.y);
            va.z = f2tf32(va.z); va.w = f2tf32(va.w);
            vb.x = f2tf32(vb.x); vb.y = f2tf32(vb.y);
            vb.z = f2tf32(vb.z); vb.w = f2tf32(vb.w);
            *(float4*)&As[r * GS + c] = va;
            *(float4*)&Bs[r * GS + c] = vb;
        }
        __syncthreads();
        if (t + 1 < T) {
            int kOff = (t + 1) * 32;
#pragma unroll
            for (int i = 0; i < 4; ++i) {
                int s = tid + 256 * i, r = s >> 3, c = (s & 7) * 4;
                fa[i] = *(const float4*)&A[(size_t)(mBase + r) * K + kOff + c];
                fb[i] = *(const float4*)&B[(size_t)(nBase + r) * K + kOff + c];
            }
        }
#pragma unroll
        for (int ks = 0; ks < 4; ++ks) {
            int k0 = ks * 8;
            uint32_t av[2][4];
#pragma unroll
            for (int mf = 0; mf < 2; ++mf) {
                int r0 = wm + mf * 16 + g;
                av[mf][0] = fbits(As[r0 * GS + k0 + tk]);
                av[mf][1] = fbits(As[(r0 + 8) * GS + k0 + tk]);
                av[mf][2] = fbits(As[r0 * GS + k0 + tk + 4]);
                av[mf][3] = fbits(As[(r0 + 8) * GS + k0 + tk + 4]);
            }
            uint32_t bv[8][2];
#pragma unroll
            for (int nf = 0; nf < 8; ++nf) {
                int rn = wn + nf * 8 + g;
                bv[nf][0] = fbits(Bs[rn * GS + k0 + tk]);
                bv[nf][1] = fbits(Bs[rn * GS + k0 + tk + 4]);
            }
#pragma unroll
            for (int mf = 0; mf < 2; ++mf)
#pragma unroll
                for (int nf = 0; nf < 8; ++nf)
                    mma_tf32(acc[mf][nf], av[mf], bv[nf]);
        }
    }

#pragma unroll
    for (int mf = 0; mf < 2; ++mf) {
        int r0 = mBase + wm + mf * 16 + g;
#pragma unroll
        for (int nf = 0; nf < 8; ++nf) {
            int c0 = nBase + wn + nf * 8 + 2 * tk;
            float o0 = acc[mf][nf][0], o1 = acc[mf][nf][1];
            float o2 = acc[mf][nf][2], o3 = acc[mf][nf][3];
            if (ROUND) { o0 = f2tf32(o0); o1 = f2tf32(o1); o2 = f2tf32(o2); o3 = f2tf32(o3); }
            *(float2*)&C[(size_t)r0 * N + c0]       = make_float2(o0, o1);
            *(float2*)&C[(size_t)(r0 + 8) * N + c0] = make_float2(o2, o3);
        }
    }
}

// ---------------------------------------------------------------------------
// TF32 sigmoid attention, cp.async double-buffered, key tile 64.
// CTA: 128 queries of one (b,h); 32 key tiles of 64. 8 warps.
// S: warp 32q x 32k (grid 4x2). PV: warp 32q x 32d (grid 4x2).
// Q fragments in registers (values pre-rounded to tf32 by producer gemm).
// Dynamic smem: Ps 128x68 | Ks[2] 64x68 | Vs[2] 64x68  = 102 KB.
// ---------------------------------------------------------------------------
#define KT 64
#define NT (SEQ / KT)           // 32
#define PST 68
#define KVT 68
#define KVBUF (KT * KVT)        // 4352 floats
#define PS_OFF 0
#define KS_OFF (128 * PST)      // 8704
#define VS_OFF (KS_OFF + 2 * KVBUF)
#define SMEM_FLOATS (VS_OFF + 2 * KVBUF)   // 26112 floats = 104448 B

__global__ __launch_bounds__(256, 1) void attn_tf32()
{
    extern __shared__ float sm[];
    float* Ps = sm + PS_OFF;

    const int tid  = threadIdx.x;
    const int lane = tid & 31;
    const int warp = tid >> 5;
    const int g    = lane >> 2;
    const int tk   = lane & 3;
    const int wm   = (warp & 3) * 32;
    const int wn2  = warp >> 2;   // 0/1: key half (S) / dim half (PV)

    const int qt = blockIdx.x, h = blockIdx.y, b = blockIdx.z;
    const float* Qg = g_Q + ((size_t)b * SEQ + qt * 128) * HID + h * HDIM;
    const float* Kg = g_K + (size_t)b * SEQ * HID + h * HDIM;
    const float* Vg = g_V + (size_t)b * SEQ * HID + h * HDIM;

    // ---- stage Q (already tf32) into Ps area, then to registers ----
#pragma unroll
    for (int i = 0; i < 8; ++i) {
        int s = tid + 256 * i, r = s >> 4, c = (s & 15) * 4;
        *(float4*)&Ps[r * PST + c] = *(const float4*)&Qg[(size_t)r * HID + c];
    }
    __syncthreads();

    uint32_t qa[8][2][4];
#pragma unroll
    for (int ks = 0; ks < 8; ++ks)
#pragma unroll
        for (int mf = 0; mf < 2; ++mf) {
            int r0 = wm + mf * 16 + g;
            qa[ks][mf][0] = fbits(Ps[r0 * PST + ks * 8 + tk]);
            qa[ks][mf][1] = fbits(Ps[(r0 + 8) * PST + ks * 8 + tk]);
            qa[ks][mf][2] = fbits(Ps[r0 * PST + ks * 8 + tk + 4]);
            qa[ks][mf][3] = fbits(Ps[(r0 + 8) * PST + ks * 8 + tk + 4]);
        }

    float oacc[2][4][4];
#pragma unroll
    for (int mf = 0; mf < 2; ++mf)
#pragma unroll
        for (int nf = 0; nf < 4; ++nf)
#pragma unroll
            for (int i = 0; i < 4; ++i) oacc[mf][nf][i] = 0.f;
    float dpart[2][2] = {{0.f, 0.f}, {0.f, 0.f}};

    // prologue: cp.async tile 0 -> buffer 0
    {
        float* Kd = sm + KS_OFF;
        float* Vd = sm + VS_OFF;
#pragma unroll
        for (int i = 0; i < 4; ++i) {
            int s = tid + 256 * i, r = s >> 4, c = (s & 15) * 4;
            cp16(&Kd[r * KVT + c], &Kg[(size_t)r * HID + c]);
            cp16(&Vd[r * KVT + c], &Vg[(size_t)r * HID + c]);
        }
        asm volatile("cp.async.commit_group;\n");
    }

    int cur = 0;
    for (int kt = 0; kt < NT; ++kt) {
        asm volatile("cp.async.wait_group 0;\n");
        __syncthreads();   // tile ready; all warps past previous PV

        if (kt + 1 < NT) {
            const float* Kn = Kg + (size_t)(kt + 1) * KT * HID;
            const float* Vn = Vg + (size_t)(kt + 1) * KT * HID;
            float* Kd = sm + KS_OFF + (cur ^ 1) * KVBUF;
            float* Vd = sm + VS_OFF + (cur ^ 1) * KVBUF;
#pragma unroll
            for (int i = 0; i < 4; ++i) {
                int s = tid + 256 * i, r = s >> 4, c = (s & 15) * 4;
                cp16(&Kd[r * KVT + c], &Kn[(size_t)r * HID + c]);
                cp16(&Vd[r * KVT + c], &Vn[(size_t)r * HID + c]);
            }
            asm volatile("cp.async.commit_group;\n");
        }

        const float* Ksc = sm + KS_OFF + cur * KVBUF;
        const float* Vsc = sm + VS_OFF + cur * KVBUF;

        // ---- S = Q K^T (warp: 32q x 32key) ----
        float sacc[2][4][4];
#pragma unroll
        for (int mf = 0; mf < 2; ++mf)
#pragma unroll
            for (int nf = 0; nf < 4; ++nf)
#pragma unroll
                for (int i = 0; i < 4; ++i) sacc[mf][nf][i] = 0.f;
#pragma unroll
        for (int ks = 0; ks < 8; ++ks) {
            uint32_t bv[4][2];
#pragma unroll
            for (int nf = 0; nf < 4; ++nf) {
                int rn = wn2 * 32 + nf * 8 + g;
                bv[nf][0] = fbits(Ksc[rn * KVT + ks * 8 + tk]);
                bv[nf][1] = fbits(Ksc[rn * KVT + ks * 8 + tk + 4]);
            }
#pragma unroll
            for (int mf = 0; mf < 2; ++mf)
#pragma unroll
                for (int nf = 0; nf < 4; ++nf)
                    mma_tf32(sacc[mf][nf], qa[ks][mf], bv[nf]);
        }

        // ---- P = sigmoid(scale*S) -> Ps, accumulate row partials ----
#pragma unroll
        for (int mf = 0; mf < 2; ++mf) {
            int r0 = wm + mf * 16 + g;
#pragma unroll
            for (int nf = 0; nf < 4; ++nf) {
                int c0 = wn2 * 32 + nf * 8 + 2 * tk;
                float p00 = f2tf32(1.f / (1.f + __expf(-SCALE * sacc[mf][nf][0])));
                float p01 = f2tf32(1.f / (1.f + __expf(-SCALE * sacc[mf][nf][1])));
                float p10 = f2tf32(1.f / (1.f + __expf(-SCALE * sacc[mf][nf][2])));
                float p11 = f2tf32(1.f / (1.f + __expf(-SCALE * sacc[mf][nf][3])));
                dpart[mf][0] += p00 + p01;
                dpart[mf][1] += p10 + p11;
                *(float2*)&Ps[r0 * PST + c0]       = make_float2(p00, p01);
                *(float2*)&Ps[(r0 + 8) * PST + c0] = make_float2(p10, p11);
            }
        }
        __syncthreads();

        // ---- O += P V (warp: 32q x 32d) ----
#pragma unroll
        for (int ks = 0; ks < 8; ++ks) {
            uint32_t pa[2][4];
#pragma unroll
            for (int mf = 0; mf < 2; ++mf) {
                int r0 = wm + mf * 16 + g;
                pa[mf][0] = fbits(Ps[r0 * PST + ks * 8 + tk]);
                pa[mf][1] = fbits(Ps[(r0 + 8) * PST + ks * 8 + tk]);
                pa[mf][2] = fbits(Ps[r0 * PST + ks * 8 + tk + 4]);
                pa[mf][3] = fbits(Ps[(r0 + 8) * PST + ks * 8 + tk + 4]);
            }
            uint32_t vb[4][2];
#pragma unroll
            for (int nf = 0; nf < 4; ++nf) {
                int cn = wn2 * 32 + nf * 8 + g;
                vb[nf][0] = fbits(Vsc[(ks * 8 + tk) * KVT + cn]);
                vb[nf][1] = fbits(Vsc[(ks * 8 + tk + 4) * KVT + cn]);
            }
#pragma unroll
            for (int mf = 0; mf < 2; ++mf)
#pragma unroll
                for (int nf = 0; nf < 4; ++nf)
                    mma_tf32(oacc[mf][nf], pa[mf], vb[nf]);
        }
        cur ^= 1;
    }

    // ---- deterministic denominator reduction ----
    __syncthreads();
    float* dp = sm + KS_OFF;   // [128][8]
#pragma unroll
    for (int mf = 0; mf < 2; ++mf) {
        dp[(wm + mf * 16 + g) * 8 + wn2 * 4 + tk]     = dpart[mf][0];
        dp[(wm + mf * 16 + g + 8) * 8 + wn2 * 4 + tk] = dpart[mf][1];
    }
    __syncthreads();

    float* Ag = g_A + ((size_t)b * SEQ + qt * 128) * HID + h * HDIM;
#pragma unroll
    for (int mf = 0; mf < 2; ++mf) {
#pragma unroll
        for (int rr = 0; rr < 2; ++rr) {
            int row = wm + mf * 16 + g + rr * 8;
            float dsum = 0.f;
#pragma unroll
            for (int j = 0; j < 8; ++j) dsum += dp[row * 8 + j];
            float inv = 1.f / (dsum + EPS);
#pragma unroll
            for (int nf = 0; nf < 4; ++nf) {
                int c0 = wn2 * 32 + nf * 8 + 2 * tk;
                float2 v = make_float2(oacc[mf][nf][rr * 2] * inv,
                                       oacc[mf][nf][rr * 2 + 1] * inv);
                *(float2*)&Ag[(size_t)row * HID + c0] = v;
            }
        }
    }
}

// ---------------------------------------------------------------------------
extern "C" void kernel_launch(void* const* d_in, const int* in_sizes, int n_in,
                              void* d_out, int out_size)
{
    float *Qp, *Kp, *Vp, *Ap;
    cudaGetSymbolAddress((void**)&Qp, g_Q);
    cudaGetSymbolAddress((void**)&Kp, g_K);
    cudaGetSymbolAddress((void**)&Vp, g_V);
    cudaGetSymbolAddress((void**)&Ap, g_A);

    cudaFuncSetAttribute(attn_tf32, cudaFuncAttributeMaxDynamicSharedMemorySize,
                         SMEM_FLOATS * 4);

    const float* x  = (const float*)d_in[0];
    const float* Wq = (const float*)d_in[1];
    const float* Wk = (const float*)d_in[2];
    const float* Wv = (const float*)d_in[3];
    const float* Wo = (const float*)d_in[4];
    float* out = (float*)d_out;

    dim3 gemmGrid(HID / 128, MTOT / 128);  // (8, 32)
    gemm_tf32<true><<<gemmGrid, 256>>>(x, Wq, Qp, MTOT, HID, HID);
    gemm_tf32<true><<<gemmGrid, 256>>>(x, Wk, Kp, MTOT, HID, HID);
    gemm_tf32<true><<<gemmGrid, 256>>>(x, Wv, Vp, MTOT, HID, HID);

    dim3 attnGrid(SEQ / 128, NHEAD, Bsz);  // (16, 16, 2)
    attn_tf32<<<attnGrid, 256, SMEM_FLOATS * 4>>>();

    gemm_tf32<false><<<gemmGrid, 256>>>(Ap, Wo, out, MTOT, HID, HID);
}

// round 6
// speedup vs baseline: 2.6861x; 1.0716x over previous
#include <cuda_runtime.h>
#include <stdint.h>
#include <math.h>

#define Bsz 2
#define SEQ 2048
#define HID 1024
#define NHEAD 16
#define HDIM 64
#define SCALE 0.125f
#define EPS 1e-6f
#define MTOT (Bsz*SEQ)   // 4096

// Scratch (device globals: allocation-free)
__device__ float g_Q[MTOT * HID];
__device__ float g_K[MTOT * HID];
__device__ float g_V[MTOT * HID];
__device__ float g_A[MTOT * HID];

// ---------------------------------------------------------------------------
// Helpers
// ---------------------------------------------------------------------------
__device__ __forceinline__ float f2tf32(float x) {
    uint32_t u;
    asm("cvt.rna.tf32.f32 %0, %1;" : "=r"(u) : "f"(x));
    return __uint_as_float(u);
}

__device__ __forceinline__ void mma_tf32(float* d, const uint32_t* a, const uint32_t* b) {
    asm volatile(
        "mma.sync.aligned.m16n8k8.row.col.f32.tf32.tf32.f32 "
        "{%0,%1,%2,%3},{%4,%5,%6,%7},{%8,%9},{%0,%1,%2,%3};\n"
        : "+f"(d[0]), "+f"(d[1]), "+f"(d[2]), "+f"(d[3])
        : "r"(a[0]), "r"(a[1]), "r"(a[2]), "r"(a[3]), "r"(b[0]), "r"(b[1]));
}

__device__ __forceinline__ uint32_t fbits(float x) { return __float_as_uint(x); }

__device__ __forceinline__ void cp16(float* smem_dst, const float* gmem_src) {
    uint32_t s = (uint32_t)__cvta_generic_to_shared(smem_dst);
    asm volatile("cp.async.cg.shared.global [%0], [%1], 16;\n" :: "r"(s), "l"(gmem_src));
}

// ---------------------------------------------------------------------------
// TF32 GEMM: C[M,N] = A[M,K] * B[N,K]^T  (row-major, K contiguous both)
// CTA tile 128x128, BK=32, 8 warps, warp tile 32x64. Register-prefetch.
// launch_bounds(256,2): cap regs at 128 -> 2 CTAs/SM (16 warps/SM).
// ---------------------------------------------------------------------------
#define GS 36

template<bool ROUND>
__global__ __launch_bounds__(256, 2) void gemm_tf32(
    const float* __restrict__ A, const float* __restrict__ B,
    float* __restrict__ C, int M, int N, int K)
{
    __shared__ float As[128 * GS];
    __shared__ float Bs[128 * GS];

    const int tid  = threadIdx.x;
    const int lane = tid & 31;
    const int warp = tid >> 5;
    const int g    = lane >> 2;
    const int tk   = lane & 3;
    const int wm   = (warp & 3) * 32;
    const int wn   = (warp >> 2) * 64;
    const int mBase = blockIdx.y * 128;
    const int nBase = blockIdx.x * 128;

    float acc[2][8][4];
#pragma unroll
    for (int mf = 0; mf < 2; ++mf)
#pragma unroll
        for (int nf = 0; nf < 8; ++nf)
#pragma unroll
            for (int i = 0; i < 4; ++i) acc[mf][nf][i] = 0.f;

    const int T = K / 32;
    float4 fa[4], fb[4];

#pragma unroll
    for (int i = 0; i < 4; ++i) {
        int s = tid + 256 * i, r = s >> 3, c = (s & 7) * 4;
        fa[i] = *(const float4*)&A[(size_t)(mBase + r) * K + c];
        fb[i] = *(const float4*)&B[(size_t)(nBase + r) * K + c];
    }

    for (int t = 0; t < T; ++t) {
        __syncthreads();
#pragma unroll
        for (int i = 0; i < 4; ++i) {
            int s = tid + 256 * i, r = s >> 3, c = (s & 7) * 4;
            float4 va = fa[i], vb = fb[i];
            va.x = f2tf32(va.x); va.y = f2tf32(va.y);
            va.z = f2tf32(va.z); va.w = f2tf32(va.w);
            vb.x = f2tf32(vb.x); vb.y = f2tf32(vb.y);
            vb.z = f2tf32(vb.z); vb.w = f2tf32(vb.w);
            *(float4*)&As[r * GS + c] = va;
            *(float4*)&Bs[r * GS + c] = vb;
        }
        __syncthreads();
        if (t + 1 < T) {
            int kOff = (t + 1) * 32;
#pragma unroll
            for (int i = 0; i < 4; ++i) {
                int s = tid + 256 * i, r = s >> 3, c = (s & 7) * 4;
                fa[i] = *(const float4*)&A[(size_t)(mBase + r) * K + kOff + c];
                fb[i] = *(const float4*)&B[(size_t)(nBase + r) * K + kOff + c];
            }
        }
#pragma unroll
        for (int ks = 0; ks < 4; ++ks) {
            int k0 = ks * 8;
            uint32_t av[2][4];
#pragma unroll
            for (int mf = 0; mf < 2; ++mf) {
                int r0 = wm + mf * 16 + g;
                av[mf][0] = fbits(As[r0 * GS + k0 + tk]);
                av[mf][1] = fbits(As[(r0 + 8) * GS + k0 + tk]);
                av[mf][2] = fbits(As[r0 * GS + k0 + tk + 4]);
                av[mf][3] = fbits(As[(r0 + 8) * GS + k0 + tk + 4]);
            }
            uint32_t bv[8][2];
#pragma unroll
            for (int nf = 0; nf < 8; ++nf) {
                int rn = wn + nf * 8 + g;
                bv[nf][0] = fbits(Bs[rn * GS + k0 + tk]);
                bv[nf][1] = fbits(Bs[rn * GS + k0 + tk + 4]);
            }
#pragma unroll
            for (int mf = 0; mf < 2; ++mf)
#pragma unroll
                for (int nf = 0; nf < 8; ++nf)
                    mma_tf32(acc[mf][nf], av[mf], bv[nf]);
        }
    }

#pragma unroll
    for (int mf = 0; mf < 2; ++mf) {
        int r0 = mBase + wm + mf * 16 + g;
#pragma unroll
        for (int nf = 0; nf < 8; ++nf) {
            int c0 = nBase + wn + nf * 8 + 2 * tk;
            float o0 = acc[mf][nf][0], o1 = acc[mf][nf][1];
            float o2 = acc[mf][nf][2], o3 = acc[mf][nf][3];
            if (ROUND) { o0 = f2tf32(o0); o1 = f2tf32(o1); o2 = f2tf32(o2); o3 = f2tf32(o3); }
            *(float2*)&C[(size_t)r0 * N + c0]       = make_float2(o0, o1);
            *(float2*)&C[(size_t)(r0 + 8) * N + c0] = make_float2(o2, o3);
        }
    }
}

// ---------------------------------------------------------------------------
// TF32 sigmoid attention, 512 threads / 16 warps, cp.async double-buffered.
// CTA: 128 queries of one (b,h); 32 key tiles of 64.
// S:  warp 16q x 32k  (8 q-groups x 2 key halves)
// PV: warp 16q x 32d  (8 q-groups x 2 dim halves)
// Q fragments in registers (32/thread). Dynamic smem 102 KB.
// ---------------------------------------------------------------------------
#define KT 64
#define NT (SEQ / KT)           // 32
#define PST 68
#define KVT 68
#define KVBUF (KT * KVT)        // 4352 floats
#define PS_OFF 0
#define KS_OFF (128 * PST)      // 8704
#define VS_OFF (KS_OFF + 2 * KVBUF)
#define SMEM_FLOATS (VS_OFF + 2 * KVBUF)   // 26112 floats = 104448 B

__global__ __launch_bounds__(512, 1) void attn_tf32()
{
    extern __shared__ float sm[];
    float* Ps = sm + PS_OFF;

    const int tid  = threadIdx.x;
    const int lane = tid & 31;
    const int warp = tid >> 5;         // 0..15
    const int g    = lane >> 2;
    const int tk   = lane & 3;
    const int wm   = (warp & 7) * 16;  // q group (16 rows)
    const int wn2  = warp >> 3;        // 0/1: key half (S) / dim half (PV)

    const int qt = blockIdx.x, h = blockIdx.y, b = blockIdx.z;
    const float* Qg = g_Q + ((size_t)b * SEQ + qt * 128) * HID + h * HDIM;
    const float* Kg = g_K + (size_t)b * SEQ * HID + h * HDIM;
    const float* Vg = g_V + (size_t)b * SEQ * HID + h * HDIM;

    // ---- stage Q (already tf32) into Ps area, then to registers ----
#pragma unroll
    for (int i = 0; i < 4; ++i) {
        int s = tid + 512 * i, r = s >> 4, c = (s & 15) * 4;
        *(float4*)&Ps[r * PST + c] = *(const float4*)&Qg[(size_t)r * HID + c];
    }
    __syncthreads();

    uint32_t qa[8][4];
#pragma unroll
    for (int ks = 0; ks < 8; ++ks) {
        int r0 = wm + g;
        qa[ks][0] = fbits(Ps[r0 * PST + ks * 8 + tk]);
        qa[ks][1] = fbits(Ps[(r0 + 8) * PST + ks * 8 + tk]);
        qa[ks][2] = fbits(Ps[r0 * PST + ks * 8 + tk + 4]);
        qa[ks][3] = fbits(Ps[(r0 + 8) * PST + ks * 8 + tk + 4]);
    }

    float oacc[4][4];
#pragma unroll
    for (int nf = 0; nf < 4; ++nf)
#pragma unroll
        for (int i = 0; i < 4; ++i) oacc[nf][i] = 0.f;
    float dpart[2] = {0.f, 0.f};

    // prologue: cp.async tile 0 -> buffer 0
    {
        float* Kd = sm + KS_OFF;
        float* Vd = sm + VS_OFF;
#pragma unroll
        for (int i = 0; i < 2; ++i) {
            int s = tid + 512 * i, r = s >> 4, c = (s & 15) * 4;
            cp16(&Kd[r * KVT + c], &Kg[(size_t)r * HID + c]);
            cp16(&Vd[r * KVT + c], &Vg[(size_t)r * HID + c]);
        }
        asm volatile("cp.async.commit_group;\n");
    }

    int cur = 0;
    for (int kt = 0; kt < NT; ++kt) {
        asm volatile("cp.async.wait_group 0;\n");
        __syncthreads();   // tile ready; all warps past previous PV

        if (kt + 1 < NT) {
            const float* Kn = Kg + (size_t)(kt + 1) * KT * HID;
            const float* Vn = Vg + (size_t)(kt + 1) * KT * HID;
            float* Kd = sm + KS_OFF + (cur ^ 1) * KVBUF;
            float* Vd = sm + VS_OFF + (cur ^ 1) * KVBUF;
#pragma unroll
            for (int i = 0; i < 2; ++i) {
                int s = tid + 512 * i, r = s >> 4, c = (s & 15) * 4;
                cp16(&Kd[r * KVT + c], &Kn[(size_t)r * HID + c]);
                cp16(&Vd[r * KVT + c], &Vn[(size_t)r * HID + c]);
            }
            asm volatile("cp.async.commit_group;\n");
        }

        const float* Ksc = sm + KS_OFF + cur * KVBUF;
        const float* Vsc = sm + VS_OFF + cur * KVBUF;

        // ---- S = Q K^T (warp: 16q x 32key) ----
        float sacc[4][4];
#pragma unroll
        for (int nf = 0; nf < 4; ++nf)
#pragma unroll
            for (int i = 0; i < 4; ++i) sacc[nf][i] = 0.f;
#pragma unroll
        for (int ks = 0; ks < 8; ++ks) {
            uint32_t bv[4][2];
#pragma unroll
            for (int nf = 0; nf < 4; ++nf) {
                int rn = wn2 * 32 + nf * 8 + g;
                bv[nf][0] = fbits(Ksc[rn * KVT + ks * 8 + tk]);
                bv[nf][1] = fbits(Ksc[rn * KVT + ks * 8 + tk + 4]);
            }
#pragma unroll
            for (int nf = 0; nf < 4; ++nf)
                mma_tf32(sacc[nf], qa[ks], bv[nf]);
        }

        // ---- P = sigmoid(scale*S) -> Ps, accumulate row partials ----
        {
            int r0 = wm + g;
#pragma unroll
            for (int nf = 0; nf < 4; ++nf) {
                int c0 = wn2 * 32 + nf * 8 + 2 * tk;
                float p00 = f2tf32(1.f / (1.f + __expf(-SCALE * sacc[nf][0])));
                float p01 = f2tf32(1.f / (1.f + __expf(-SCALE * sacc[nf][1])));
                float p10 = f2tf32(1.f / (1.f + __expf(-SCALE * sacc[nf][2])));
                float p11 = f2tf32(1.f / (1.f + __expf(-SCALE * sacc[nf][3])));
                dpart[0] += p00 + p01;
                dpart[1] += p10 + p11;
                *(float2*)&Ps[r0 * PST + c0]       = make_float2(p00, p01);
                *(float2*)&Ps[(r0 + 8) * PST + c0] = make_float2(p10, p11);
            }
        }
        __syncthreads();

        // ---- O += P V (warp: 16q x 32d) ----
#pragma unroll
        for (int ks = 0; ks < 8; ++ks) {
            uint32_t pa[4];
            {
                int r0 = wm + g;
                pa[0] = fbits(Ps[r0 * PST + ks * 8 + tk]);
                pa[1] = fbits(Ps[(r0 + 8) * PST + ks * 8 + tk]);
                pa[2] = fbits(Ps[r0 * PST + ks * 8 + tk + 4]);
                pa[3] = fbits(Ps[(r0 + 8) * PST + ks * 8 + tk + 4]);
            }
            uint32_t vb[4][2];
#pragma unroll
            for (int nf = 0; nf < 4; ++nf) {
                int cn = wn2 * 32 + nf * 8 + g;
                vb[nf][0] = fbits(Vsc[(ks * 8 + tk) * KVT + cn]);
                vb[nf][1] = fbits(Vsc[(ks * 8 + tk + 4) * KVT + cn]);
            }
#pragma unroll
            for (int nf = 0; nf < 4; ++nf)
                mma_tf32(oacc[nf], pa, vb[nf]);
        }
        cur ^= 1;
    }

    // ---- deterministic denominator reduction ----
    __syncthreads();
    float* dp = sm + KS_OFF;   // [128][8]
    dp[(wm + g) * 8 + wn2 * 4 + tk]     = dpart[0];
    dp[(wm + g + 8) * 8 + wn2 * 4 + tk] = dpart[1];
    __syncthreads();

    float* Ag = g_A + ((size_t)b * SEQ + qt * 128) * HID + h * HDIM;
#pragma unroll
    for (int rr = 0; rr < 2; ++rr) {
        int row = wm + g + rr * 8;
        float dsum = 0.f;
#pragma unroll
        for (int j = 0; j < 8; ++j) dsum += dp[row * 8 + j];
        float inv = 1.f / (dsum + EPS);
#pragma unroll
        for (int nf = 0; nf < 4; ++nf) {
            int c0 = wn2 * 32 + nf * 8 + 2 * tk;
            float2 v = make_float2(oacc[nf][rr * 2] * inv,
                                   oacc[nf][rr * 2 + 1] * inv);
            *(float2*)&Ag[(size_t)row * HID + c0] = v;
        }
    }
}

// ---------------------------------------------------------------------------
extern "C" void kernel_launch(void* const* d_in, const int* in_sizes, int n_in,
                              void* d_out, int out_size)
{
    float *Qp, *Kp, *Vp, *Ap;
    cudaGetSymbolAddress((void**)&Qp, g_Q);
    cudaGetSymbolAddress((void**)&Kp, g_K);
    cudaGetSymbolAddress((void**)&Vp, g_V);
    cudaGetSymbolAddress((void**)&Ap, g_A);

    cudaFuncSetAttribute(attn_tf32, cudaFuncAttributeMaxDynamicSharedMemorySize,
                         SMEM_FLOATS * 4);

    const float* x  = (const float*)d_in[0];
    const float* Wq = (const float*)d_in[1];
    const float* Wk = (const float*)d_in[2];
    const float* Wv = (const float*)d_in[3];
    const float* Wo = (const float*)d_in[4];
    float* out = (float*)d_out;

    dim3 gemmGrid(HID / 128, MTOT / 128);  // (8, 32)
    gemm_tf32<true><<<gemmGrid, 256>>>(x, Wq, Qp, MTOT, HID, HID);
    gemm_tf32<true><<<gemmGrid, 256>>>(x, Wk, Kp, MTOT, HID, HID);
    gemm_tf32<true><<<gemmGrid, 256>>>(x, Wv, Vp, MTOT, HID, HID);

    dim3 attnGrid(SEQ / 128, NHEAD, Bsz);  // (16, 16, 2)
    attn_tf32<<<attnGrid, 512, SMEM_FLOATS * 4>>>();

    gemm_tf32<false><<<gemmGrid, 256>>>(Ap, Wo, out, MTOT, HID, HID);
}

// round 7
// speedup vs baseline: 2.8348x; 1.0554x over previous
#include <cuda_runtime.h>
#include <stdint.h>
#include <math.h>

#define Bsz 2
#define SEQ 2048
#define HID 1024
#define NHEAD 16
#define HDIM 64
#define SCALE 0.125f
#define EPS 1e-6f
#define MTOT (Bsz*SEQ)   // 4096

// Scratch (device globals: allocation-free)
__device__ float g_Q[MTOT * HID];
__device__ float g_K[MTOT * HID];
__device__ float g_V[MTOT * HID];
__device__ float g_A[MTOT * HID];

// ---------------------------------------------------------------------------
// Helpers
// ---------------------------------------------------------------------------
__device__ __forceinline__ float f2tf32(float x) {
    uint32_t u;
    asm("cvt.rna.tf32.f32 %0, %1;" : "=r"(u) : "f"(x));
    return __uint_as_float(u);
}

__device__ __forceinline__ void mma_tf32(float* d, const uint32_t* a, const uint32_t* b) {
    asm volatile(
        "mma.sync.aligned.m16n8k8.row.col.f32.tf32.tf32.f32 "
        "{%0,%1,%2,%3},{%4,%5,%6,%7},{%8,%9},{%0,%1,%2,%3};\n"
        : "+f"(d[0]), "+f"(d[1]), "+f"(d[2]), "+f"(d[3])
        : "r"(a[0]), "r"(a[1]), "r"(a[2]), "r"(a[3]), "r"(b[0]), "r"(b[1]));
}

__device__ __forceinline__ uint32_t fbits(float x) { return __float_as_uint(x); }

__device__ __forceinline__ void cp16(float* smem_dst, const float* gmem_src) {
    uint32_t s = (uint32_t)__cvta_generic_to_shared(smem_dst);
    asm volatile("cp.async.cg.shared.global [%0], [%1], 16;\n" :: "r"(s), "l"(gmem_src));
}

// ---------------------------------------------------------------------------
// TF32 GEMM: C[M,N] = A[M,K] * B[N,K]^T  (unchanged from R6: 2 CTAs/SM)
// ---------------------------------------------------------------------------
#define GS 36

template<bool ROUND>
__global__ __launch_bounds__(256, 2) void gemm_tf32(
    const float* __restrict__ A, const float* __restrict__ B,
    float* __restrict__ C, int M, int N, int K)
{
    __shared__ float As[128 * GS];
    __shared__ float Bs[128 * GS];

    const int tid  = threadIdx.x;
    const int lane = tid & 31;
    const int warp = tid >> 5;
    const int g    = lane >> 2;
    const int tk   = lane & 3;
    const int wm   = (warp & 3) * 32;
    const int wn   = (warp >> 2) * 64;
    const int mBase = blockIdx.y * 128;
    const int nBase = blockIdx.x * 128;

    float acc[2][8][4];
#pragma unroll
    for (int mf = 0; mf < 2; ++mf)
#pragma unroll
        for (int nf = 0; nf < 8; ++nf)
#pragma unroll
            for (int i = 0; i < 4; ++i) acc[mf][nf][i] = 0.f;

    const int T = K / 32;
    float4 fa[4], fb[4];

#pragma unroll
    for (int i = 0; i < 4; ++i) {
        int s = tid + 256 * i, r = s >> 3, c = (s & 7) * 4;
        fa[i] = *(const float4*)&A[(size_t)(mBase + r) * K + c];
        fb[i] = *(const float4*)&B[(size_t)(nBase + r) * K + c];
    }

    for (int t = 0; t < T; ++t) {
        __syncthreads();
#pragma unroll
        for (int i = 0; i < 4; ++i) {
            int s = tid + 256 * i, r = s >> 3, c = (s & 7) * 4;
            float4 va = fa[i], vb = fb[i];
            va.x = f2tf32(va.x); va.y = f2tf32(va.y);
            va.z = f2tf32(va.z); va.w = f2tf32(va.w);
            vb.x = f2tf32(vb.x); vb.y = f2tf32(vb.y);
            vb.z = f2tf32(vb.z); vb.w = f2tf32(vb.w);
            *(float4*)&As[r * GS + c] = va;
            *(float4*)&Bs[r * GS + c] = vb;
        }
        __syncthreads();
        if (t + 1 < T) {
            int kOff = (t + 1) * 32;
#pragma unroll
            for (int i = 0; i < 4; ++i) {
                int s = tid + 256 * i, r = s >> 3, c = (s & 7) * 4;
                fa[i] = *(const float4*)&A[(size_t)(mBase + r) * K + kOff + c];
                fb[i] = *(const float4*)&B[(size_t)(nBase + r) * K + kOff + c];
            }
        }
#pragma unroll
        for (int ks = 0; ks < 4; ++ks) {
            int k0 = ks * 8;
            uint32_t av[2][4];
#pragma unroll
            for (int mf = 0; mf < 2; ++mf) {
                int r0 = wm + mf * 16 + g;
                av[mf][0] = fbits(As[r0 * GS + k0 + tk]);
                av[mf][1] = fbits(As[(r0 + 8) * GS + k0 + tk]);
                av[mf][2] = fbits(As[r0 * GS + k0 + tk + 4]);
                av[mf][3] = fbits(As[(r0 + 8) * GS + k0 + tk + 4]);
            }
            uint32_t bv[8][2];
#pragma unroll
            for (int nf = 0; nf < 8; ++nf) {
                int rn = wn + nf * 8 + g;
                bv[nf][0] = fbits(Bs[rn * GS + k0 + tk]);
                bv[nf][1] = fbits(Bs[rn * GS + k0 + tk + 4]);
            }
#pragma unroll
            for (int mf = 0; mf < 2; ++mf)
#pragma unroll
                for (int nf = 0; nf < 8; ++nf)
                    mma_tf32(acc[mf][nf], av[mf], bv[nf]);
        }
    }

#pragma unroll
    for (int mf = 0; mf < 2; ++mf) {
        int r0 = mBase + wm + mf * 16 + g;
#pragma unroll
        for (int nf = 0; nf < 8; ++nf) {
            int c0 = nBase + wn + nf * 8 + 2 * tk;
            float o0 = acc[mf][nf][0], o1 = acc[mf][nf][1];
            float o2 = acc[mf][nf][2], o3 = acc[mf][nf][3];
            if (ROUND) { o0 = f2tf32(o0); o1 = f2tf32(o1); o2 = f2tf32(o2); o3 = f2tf32(o3); }
            *(float2*)&C[(size_t)r0 * N + c0]       = make_float2(o0, o1);
            *(float2*)&C[(size_t)(r0 + 8) * N + c0] = make_float2(o2, o3);
        }
    }
}

// ---------------------------------------------------------------------------
// TF32 sigmoid attention v3: warp-autonomous tiles, ONE barrier per key tile.
// CTA: 256 queries of one (b,h), 512 threads / 16 warps.
// Warp w owns q-rows [w*16, w*16+16): S = 16q x 64k, PV = 16q x 64d.
// P never crosses warps: warp-private smem scratch (syncwarp only).
// Denominators: quad shfl reduction (no smem, no barrier).
// smem: K[2] 64x68 | V[2] 64x68 | Pw 16x(16x68)  = 139,264 B.
// ---------------------------------------------------------------------------
#define QT 256
#define KT 64
#define NT (SEQ / KT)            // 32
#define KVT 68
#define KVBUF (KT * KVT)         // 4352 floats
#define VS_OFF (2 * KVBUF)       // 8704
#define P_OFF  (4 * KVBUF)       // 17408
#define PWSTRIDE (16 * KVT)      // 1088 floats per warp
#define SMEM_FLOATS (P_OFF + 16 * PWSTRIDE)   // 34816 floats = 139,264 B

__global__ __launch_bounds__(512, 1) void attn_tf32()
{
    extern __shared__ float sm[];

    const int tid  = threadIdx.x;
    const int lane = tid & 31;
    const int warp = tid >> 5;        // 0..15
    const int g    = lane >> 2;       // 0..7
    const int tk   = lane & 3;        // 0..3
    const int wq   = warp * 16;       // q-row base within CTA

    const int qt = blockIdx.x, h = blockIdx.y, b = blockIdx.z;
    const float* Qg = g_Q + ((size_t)b * SEQ + qt * QT) * HID + h * HDIM;
    const float* Kg = g_K + (size_t)b * SEQ * HID + h * HDIM;
    const float* Vg = g_V + (size_t)b * SEQ * HID + h * HDIM;

    // ---- stage Q (256x64, already tf32) into smem [reuses KV region] ----
#pragma unroll
    for (int i = 0; i < 8; ++i) {
        int s = tid + 512 * i, r = s >> 4, c = (s & 15) * 4;
        *(float4*)&sm[r * KVT + c] = *(const float4*)&Qg[(size_t)r * HID + c];
    }
    __syncthreads();

    uint32_t qa[8][4];
#pragma unroll
    for (int ks = 0; ks < 8; ++ks) {
        int r0 = wq + g;
        qa[ks][0] = fbits(sm[r0 * KVT + ks * 8 + tk]);
        qa[ks][1] = fbits(sm[(r0 + 8) * KVT + ks * 8 + tk]);
        qa[ks][2] = fbits(sm[r0 * KVT + ks * 8 + tk + 4]);
        qa[ks][3] = fbits(sm[(r0 + 8) * KVT + ks * 8 + tk + 4]);
    }
    __syncthreads();   // staging region free before KV prologue

    float oacc[8][4];
#pragma unroll
    for (int nf = 0; nf < 8; ++nf)
#pragma unroll
        for (int i = 0; i < 4; ++i) oacc[nf][i] = 0.f;
    float dpart0 = 0.f, dpart1 = 0.f;

    // prologue: cp.async tile 0 -> buffer 0
    {
        float* Kd = sm;
        float* Vd = sm + VS_OFF;
#pragma unroll
        for (int i = 0; i < 2; ++i) {
            int s = tid + 512 * i, r = s >> 4, c = (s & 15) * 4;
            cp16(&Kd[r * KVT + c], &Kg[(size_t)r * HID + c]);
            cp16(&Vd[r * KVT + c], &Vg[(size_t)r * HID + c]);
        }
        asm volatile("cp.async.commit_group;\n");
    }

    float* Pw = sm + P_OFF + warp * PWSTRIDE;
    int cur = 0;

    for (int kt = 0; kt < NT; ++kt) {
        asm volatile("cp.async.wait_group 0;\n");
        __syncthreads();   // single CTA barrier per tile

        if (kt + 1 < NT) {
            const float* Kn = Kg + (size_t)(kt + 1) * KT * HID;
            const float* Vn = Vg + (size_t)(kt + 1) * KT * HID;
            float* Kd = sm + (cur ^ 1) * KVBUF;
            float* Vd = sm + VS_OFF + (cur ^ 1) * KVBUF;
#pragma unroll
            for (int i = 0; i < 2; ++i) {
                int s = tid + 512 * i, r = s >> 4, c = (s & 15) * 4;
                cp16(&Kd[r * KVT + c], &Kn[(size_t)r * HID + c]);
                cp16(&Vd[r * KVT + c], &Vn[(size_t)r * HID + c]);
            }
            asm volatile("cp.async.commit_group;\n");
        }

        const float* Ksc = sm + cur * KVBUF;
        const float* Vsc = sm + VS_OFF + cur * KVBUF;

        // ---- S = Q K^T : warp computes 16q x 64k ----
        float sacc[8][4];
#pragma unroll
        for (int nf = 0; nf < 8; ++nf)
#pragma unroll
            for (int i = 0; i < 4; ++i) sacc[nf][i] = 0.f;
#pragma unroll
        for (int nf = 0; nf < 8; ++nf) {
            int rn = nf * 8 + g;
#pragma unroll
            for (int ks = 0; ks < 8; ++ks) {
                uint32_t bv[2];
                bv[0] = fbits(Ksc[rn * KVT + ks * 8 + tk]);
                bv[1] = fbits(Ksc[rn * KVT + ks * 8 + tk + 4]);
                mma_tf32(sacc[nf], qa[ks], bv);
            }
        }

        // ---- P = sigmoid(scale*S) -> warp-private smem + row partials ----
#pragma unroll
        for (int nf = 0; nf < 8; ++nf) {
            int c0 = nf * 8 + 2 * tk;
            float p00 = f2tf32(1.f / (1.f + __expf(-SCALE * sacc[nf][0])));
            float p01 = f2tf32(1.f / (1.f + __expf(-SCALE * sacc[nf][1])));
            float p10 = f2tf32(1.f / (1.f + __expf(-SCALE * sacc[nf][2])));
            float p11 = f2tf32(1.f / (1.f + __expf(-SCALE * sacc[nf][3])));
            dpart0 += p00 + p01;
            dpart1 += p10 + p11;
            *(float2*)&Pw[g * KVT + c0]       = make_float2(p00, p01);
            *(float2*)&Pw[(g + 8) * KVT + c0] = make_float2(p10, p11);
        }
        __syncwarp();

        // ---- O += P V : warp computes 16q x 64d ----
#pragma unroll
        for (int ks = 0; ks < 8; ++ks) {
            uint32_t pa[4];
            pa[0] = fbits(Pw[g * KVT + ks * 8 + tk]);
            pa[1] = fbits(Pw[(g + 8) * KVT + ks * 8 + tk]);
            pa[2] = fbits(Pw[g * KVT + ks * 8 + tk + 4]);
            pa[3] = fbits(Pw[(g + 8) * KVT + ks * 8 + tk + 4]);
#pragma unroll
            for (int nf = 0; nf < 8; ++nf) {
                int cn = nf * 8 + g;
                uint32_t vb[2];
                vb[0] = fbits(Vsc[(ks * 8 + tk) * KVT + cn]);
                vb[1] = fbits(Vsc[(ks * 8 + tk + 4) * KVT + cn]);
                mma_tf32(oacc[nf], pa, vb);
            }
        }
        __syncwarp();   // Pw reuse next tile (same warp)
        cur ^= 1;
    }

    // ---- denominators: reduce across the 4 lanes of each row quad ----
    float d0 = dpart0;
    d0 += __shfl_xor_sync(0xFFFFFFFFu, d0, 1);
    d0 += __shfl_xor_sync(0xFFFFFFFFu, d0, 2);
    float d1 = dpart1;
    d1 += __shfl_xor_sync(0xFFFFFFFFu, d1, 1);
    d1 += __shfl_xor_sync(0xFFFFFFFFu, d1, 2);
    float inv0 = 1.f / (d0 + EPS);
    float inv1 = 1.f / (d1 + EPS);

    // ---- epilogue ----
    float* Ag = g_A + ((size_t)b * SEQ + qt * QT) * HID + h * HDIM;
    int row0 = wq + g, row1 = wq + g + 8;
#pragma unroll
    for (int nf = 0; nf < 8; ++nf) {
        int c0 = nf * 8 + 2 * tk;
        *(float2*)&Ag[(size_t)row0 * HID + c0] =
            make_float2(oacc[nf][0] * inv0, oacc[nf][1] * inv0);
        *(float2*)&Ag[(size_t)row1 * HID + c0] =
            make_float2(oacc[nf][2] * inv1, oacc[nf][3] * inv1);
    }
}

// ---------------------------------------------------------------------------
extern "C" void kernel_launch(void* const* d_in, const int* in_sizes, int n_in,
                              void* d_out, int out_size)
{
    float *Qp, *Kp, *Vp, *Ap;
    cudaGetSymbolAddress((void**)&Qp, g_Q);
    cudaGetSymbolAddress((void**)&Kp, g_K);
    cudaGetSymbolAddress((void**)&Vp, g_V);
    cudaGetSymbolAddress((void**)&Ap, g_A);

    cudaFuncSetAttribute(attn_tf32, cudaFuncAttributeMaxDynamicSharedMemorySize,
                         SMEM_FLOATS * 4);

    const float* x  = (const float*)d_in[0];
    const float* Wq = (const float*)d_in[1];
    const float* Wk = (const float*)d_in[2];
    const float* Wv = (const float*)d_in[3];
    const float* Wo = (const float*)d_in[4];
    float* out = (float*)d_out;

    dim3 gemmGrid(HID / 128, MTOT / 128);  // (8, 32)
    gemm_tf32<true><<<gemmGrid, 256>>>(x, Wq, Qp, MTOT, HID, HID);
    gemm_tf32<true><<<gemmGrid, 256>>>(x, Wk, Kp, MTOT, HID, HID);
    gemm_tf32<true><<<gemmGrid, 256>>>(x, Wv, Vp, MTOT, HID, HID);

    dim3 attnGrid(SEQ / QT, NHEAD, Bsz);   // (8, 16, 2)
    attn_tf32<<<attnGrid, 512, SMEM_FLOATS * 4>>>();

    gemm_tf32<false><<<gemmGrid, 256>>>(Ap, Wo, out, MTOT, HID, HID);
}

// round 10
// speedup vs baseline: 4.5641x; 1.6100x over previous
#include <cuda_runtime.h>
#include <cuda_fp16.h>
#include <stdint.h>
#include <math.h>

#define Bsz 2
#define SEQ 2048
#define HID 1024
#define NHEAD 16
#define HDIM 64
#define SCALE 0.125f
#define EPS 1e-6f
#define MTOT (Bsz*SEQ)   // 4096

// Scratch (device globals: allocation-free)
__device__ __half g_Q[MTOT * HID];
__device__ __half g_K[MTOT * HID];
__device__ __half g_V[MTOT * HID];
__device__ __half g_A[MTOT * HID];
__device__ __half g_X[MTOT * HID];       // fp16 x
__device__ __half g_W[4 * HID * HID];    // fp16 Wq,Wk,Wv,Wo

// ---------------------------------------------------------------------------
// Helpers
// ---------------------------------------------------------------------------
__device__ __forceinline__ void mma_f16(float* d, const uint32_t* a, const uint32_t* b) {
    asm volatile(
        "mma.sync.aligned.m16n8k16.row.col.f32.f16.f16.f32 "
        "{%0,%1,%2,%3},{%4,%5,%6,%7},{%8,%9},{%0,%1,%2,%3};\n"
        : "+f"(d[0]), "+f"(d[1]), "+f"(d[2]), "+f"(d[3])
        : "r"(a[0]), "r"(a[1]), "r"(a[2]), "r"(a[3]), "r"(b[0]), "r"(b[1]));
}

__device__ __forceinline__ void cp16(void* smem_dst, const void* gmem_src) {
    uint32_t s = (uint32_t)__cvta_generic_to_shared(smem_dst);
    asm volatile("cp.async.cg.shared.global [%0], [%1], 16;\n" :: "r"(s), "l"(gmem_src));
}

__device__ __forceinline__ uint32_t h2u(__half2 h) { return *reinterpret_cast<uint32_t*>(&h); }

// ---------------------------------------------------------------------------
// f32 -> f16 conversion pre-pass
// ---------------------------------------------------------------------------
__global__ void to_half_k(const float4* __restrict__ in, uint2* __restrict__ out, int n4)
{
    for (int i = blockIdx.x * blockDim.x + threadIdx.x; i < n4; i += gridDim.x * blockDim.x) {
        float4 v = in[i];
        out[i] = make_uint2(h2u(__floats2half2_rn(v.x, v.y)),
                            h2u(__floats2half2_rn(v.z, v.w)));
    }
}

// ---------------------------------------------------------------------------
// FP16 GEMM: C[M,N] = A[M,K] * B[N,K]^T   (A,B fp16 in gmem, K contiguous)
// CTA tile 128x128, BK=64 halfs, 8 warps, warp tile 32x64. Register-prefetch.
// HOUT: write C as fp16 (Q/K/V projections) else fp32 (final output).
// ---------------------------------------------------------------------------
#define GS2 72   // smem row stride in halfs (144 B): frag banks 4g+tk distinct

template<bool HOUT>
__global__ __launch_bounds__(256, 2) void gemm_f16(
    const __half* __restrict__ A, const __half* __restrict__ B,
    void* __restrict__ Cv, int M, int N, int K)
{
    __shared__ __half As[128 * GS2];
    __shared__ __half Bs[128 * GS2];

    const int tid  = threadIdx.x;
    const int lane = tid & 31;
    const int warp = tid >> 5;
    const int g    = lane >> 2;
    const int tk   = lane & 3;
    const int wm   = (warp & 3) * 32;
    const int wn   = (warp >> 2) * 64;
    const int mBase = blockIdx.y * 128;
    const int nBase = blockIdx.x * 128;

    float acc[2][8][4];
#pragma unroll
    for (int mf = 0; mf < 2; ++mf)
#pragma unroll
        for (int nf = 0; nf < 8; ++nf)
#pragma unroll
            for (int i = 0; i < 4; ++i) acc[mf][nf][i] = 0.f;

    const int T = K / 64;   // 16
    uint4 fa[4], fb[4];

    // prologue: k-tile 0 (128 rows x 64 halfs = 1024 uint4 slots / tensor)
#pragma unroll
    for (int i = 0; i < 4; ++i) {
        int s = tid + 256 * i, r = s >> 3, c8 = s & 7;
        fa[i] = *(const uint4*)&A[(size_t)(mBase + r) * K + c8 * 8];
        fb[i] = *(const uint4*)&B[(size_t)(nBase + r) * K + c8 * 8];
    }

    for (int t = 0; t < T; ++t) {
        __syncthreads();
#pragma unroll
        for (int i = 0; i < 4; ++i) {
            int s = tid + 256 * i, r = s >> 3, c8 = s & 7;
            *(uint4*)&As[r * GS2 + c8 * 8] = fa[i];
            *(uint4*)&Bs[r * GS2 + c8 * 8] = fb[i];
        }
        __syncthreads();
        if (t + 1 < T) {
            int kOff = (t + 1) * 64;
#pragma unroll
            for (int i = 0; i < 4; ++i) {
                int s = tid + 256 * i, r = s >> 3, c8 = s & 7;
                fa[i] = *(const uint4*)&A[(size_t)(mBase + r) * K + kOff + c8 * 8];
                fb[i] = *(const uint4*)&B[(size_t)(nBase + r) * K + kOff + c8 * 8];
            }
        }
#pragma unroll
        for (int ks = 0; ks < 4; ++ks) {
            int k0 = ks * 16 + 2 * tk;
            uint32_t av[2][4];
#pragma unroll
            for (int mf = 0; mf < 2; ++mf) {
                int r0 = wm + mf * 16 + g;
                av[mf][0] = *(const uint32_t*)&As[r0 * GS2 + k0];
                av[mf][1] = *(const uint32_t*)&As[(r0 + 8) * GS2 + k0];
                av[mf][2] = *(const uint32_t*)&As[r0 * GS2 + k0 + 8];
                av[mf][3] = *(const uint32_t*)&As[(r0 + 8) * GS2 + k0 + 8];
            }
            uint32_t bv[8][2];
#pragma unroll
            for (int nf = 0; nf < 8; ++nf) {
                int rn = wn + nf * 8 + g;
                bv[nf][0] = *(const uint32_t*)&Bs[rn * GS2 + k0];
                bv[nf][1] = *(const uint32_t*)&Bs[rn * GS2 + k0 + 8];
            }
#pragma unroll
            for (int mf = 0; mf < 2; ++mf)
#pragma unroll
                for (int nf = 0; nf < 8; ++nf)
                    mma_f16(acc[mf][nf], av[mf], bv[nf]);
        }
    }

#pragma unroll
    for (int mf = 0; mf < 2; ++mf) {
        int r0 = mBase + wm + mf * 16 + g;
#pragma unroll
        for (int nf = 0; nf < 8; ++nf) {
            int c0 = nBase + wn + nf * 8 + 2 * tk;
            if (HOUT) {
                __half* C = (__half*)Cv;
                *(uint32_t*)&C[(size_t)r0 * N + c0] =
                    h2u(__floats2half2_rn(acc[mf][nf][0], acc[mf][nf][1]));
                *(uint32_t*)&C[(size_t)(r0 + 8) * N + c0] =
                    h2u(__floats2half2_rn(acc[mf][nf][2], acc[mf][nf][3]));
            } else {
                float* C = (float*)Cv;
                *(float2*)&C[(size_t)r0 * N + c0] = make_float2(acc[mf][nf][0], acc[mf][nf][1]);
                *(float2*)&C[(size_t)(r0 + 8) * N + c0] = make_float2(acc[mf][nf][2], acc[mf][nf][3]);
            }
        }
    }
}

// ---------------------------------------------------------------------------
// FP16 sigmoid attention: warp-autonomous tiles, ONE CTA barrier per key tile.
// CTA: 256 queries of one (b,h), 512 threads / 16 warps.
// Warp w owns q-rows [w*16, w*16+16): S = 16q x 64k, PV = 16q x 64d (m16n8k16).
// V stored transposed-in-pairs: Vt[d][key/2] half2 {V[k][d], V[k+1][d]},
// built in-registers during the PREVIOUS tile (double-buffered, barrier-ordered).
// smem: Ks[2] 64x72h | Vt[2] 64x37w | Pw 16x(16x72h); Q staged over Pw.
// ---------------------------------------------------------------------------
#define AQT 256
#define ANT 32                    // SEQ / 64
#define KSR 72                    // Ks/Pw/Qs row stride (halfs)
#define KSBUF (64 * KSR)          // 4608 halfs per K buffer
#define VTS 37                    // Vt row stride (uint32)
#define VTBUF (64 * VTS)          // 2368 uint32 per V buffer
#define ASM_VT (2 * KSBUF * 2)            // 18432 B
#define ASM_PW (ASM_VT + 2 * VTBUF * 4)   // 37376 B
#define PWH (16 * KSR)            // 1152 halfs per warp
#define ASM_TOTAL (ASM_PW + 16 * PWH * 2) // 74240 B

__device__ __forceinline__ void store_vt(uint32_t* Vt, uint2 va, uint2 vb, int d0, int key2)
{
    __half2 a01 = *reinterpret_cast<__half2*>(&va.x);
    __half2 a23 = *reinterpret_cast<__half2*>(&va.y);
    __half2 b01 = *reinterpret_cast<__half2*>(&vb.x);
    __half2 b23 = *reinterpret_cast<__half2*>(&vb.y);
    Vt[(d0 + 0) * VTS + key2] = h2u(__halves2half2(a01.x, b01.x));
    Vt[(d0 + 1) * VTS + key2] = h2u(__halves2half2(a01.y, b01.y));
    Vt[(d0 + 2) * VTS + key2] = h2u(__halves2half2(a23.x, b23.x));
    Vt[(d0 + 3) * VTS + key2] = h2u(__halves2half2(a23.y, b23.y));
}

__global__ __launch_bounds__(512, 1) void attn_f16()
{
    extern __shared__ char smb[];
    __half*   KsBase = (__half*)smb;
    uint32_t* VtBase = (uint32_t*)(smb + ASM_VT);
    __half*   PwBase = (__half*)(smb + ASM_PW);
    __half*   Qs     = (__half*)(smb + ASM_PW);   // staging overlay

    const int tid  = threadIdx.x;
    const int lane = tid & 31;
    const int warp = tid >> 5;
    const int g    = lane >> 2;
    const int tk   = lane & 3;
    const int wq   = warp * 16;

    const int qt = blockIdx.x, h = blockIdx.y, b = blockIdx.z;
    const __half* Qg = g_Q + ((size_t)b * SEQ + qt * AQT) * HID + h * HDIM;
    const __half* Kg = g_K + (size_t)b * SEQ * HID + h * HDIM;
    const __half* Vg = g_V + (size_t)b * SEQ * HID + h * HDIM;

    // ---- stage Q (256x64 halfs) and extract fragments ----
#pragma unroll
    for (int i = 0; i < 4; ++i) {
        int s = tid + 512 * i, r = s >> 3, c8 = s & 7;
        *(uint4*)&Qs[r * KSR + c8 * 8] = *(const uint4*)&Qg[(size_t)r * HID + c8 * 8];
    }
    __syncthreads();

    uint32_t qa[4][4];
#pragma unroll
    for (int ks = 0; ks < 4; ++ks) {
        int r0 = wq + g, base = ks * 16 + 2 * tk;
        qa[ks][0] = *(const uint32_t*)&Qs[r0 * KSR + base];
        qa[ks][1] = *(const uint32_t*)&Qs[(r0 + 8) * KSR + base];
        qa[ks][2] = *(const uint32_t*)&Qs[r0 * KSR + base + 8];
        qa[ks][3] = *(const uint32_t*)&Qs[(r0 + 8) * KSR + base + 8];
    }
    __syncthreads();   // Pw region free

    float oacc[8][4];
#pragma unroll
    for (int nf = 0; nf < 8; ++nf)
#pragma unroll
        for (int i = 0; i < 4; ++i) oacc[nf][i] = 0.f;
    float dp0 = 0.f, dp1 = 0.f;

    // V transpose mapping: thread covers keys (2*vkey2, 2*vkey2+1), dims vd0..vd0+3
    const int vkey2 = tid >> 4;        // 0..31
    const int vd0   = (tid & 15) * 4;  // 0..60
    uint2 va, vb2;

    // ---- prologue: V(0) transposed + K(0) cp.async ----
    {
        const __half* Vr = Vg + (size_t)(2 * vkey2) * HID + vd0;
        va  = *(const uint2*)Vr;
        vb2 = *(const uint2*)(Vr + HID);
        store_vt(VtBase, va, vb2, vd0, vkey2);
        cp16(&KsBase[(tid >> 3) * KSR + (tid & 7) * 8],
             &Kg[(size_t)(tid >> 3) * HID + (tid & 7) * 8]);
        asm volatile("cp.async.commit_group;\n");
    }

    __half* Pw = PwBase + warp * PWH;

    for (int kt = 0; kt < ANT; ++kt) {
        asm volatile("cp.async.wait_group 0;\n" ::: "memory");
        __syncthreads();   // K(kt) ready, Vt[kt&1] complete, Pw free

        const bool nxt = (kt + 1 < ANT);
        if (nxt) {
            const __half* Vr = Vg + (size_t)((kt + 1) * 64 + 2 * vkey2) * HID + vd0;
            va  = *(const uint2*)Vr;
            vb2 = *(const uint2*)(Vr + HID);
            const __half* Kn = Kg + (size_t)(kt + 1) * 64 * HID;
            cp16(&KsBase[((kt + 1) & 1) * KSBUF + (tid >> 3) * KSR + (tid & 7) * 8],
                 &Kn[(size_t)(tid >> 3) * HID + (tid & 7) * 8]);
            asm volatile("cp.async.commit_group;\n");
        }

        const __half*   Ksc = KsBase + (kt & 1) * KSBUF;
        const uint32_t* Vtc = VtBase + (kt & 1) * VTBUF;

        // ---- S = Q K^T : 16q x 64k, 32 mmas ----
        float sacc[8][4];
#pragma unroll
        for (int nf = 0; nf < 8; ++nf)
#pragma unroll
            for (int i = 0; i < 4; ++i) sacc[nf][i] = 0.f;
#pragma unroll
        for (int nf = 0; nf < 8; ++nf) {
            int rn = nf * 8 + g;
#pragma unroll
            for (int ks = 0; ks < 4; ++ks) {
                int k0 = ks * 16 + 2 * tk;
                uint32_t bv[2];
                bv[0] = *(const uint32_t*)&Ksc[rn * KSR + k0];
                bv[1] = *(const uint32_t*)&Ksc[rn * KSR + k0 + 8];
                mma_f16(sacc[nf], qa[ks], bv);
            }
        }

        // stash V(kt+1) transposed into the other buffer (ordered by next barrier)
        if (nxt) store_vt(VtBase + ((kt + 1) & 1) * VTBUF, va, vb2, vd0, vkey2);

        // ---- P = sigmoid(scale*S) -> warp-private fp16 + row partials ----
#pragma unroll
        for (int nf = 0; nf < 8; ++nf) {
            int c0 = nf * 8 + 2 * tk;
            float p00 = 1.f / (1.f + __expf(-SCALE * sacc[nf][0]));
            float p01 = 1.f / (1.f + __expf(-SCALE * sacc[nf][1]));
            float p10 = 1.f / (1.f + __expf(-SCALE * sacc[nf][2]));
            float p11 = 1.f / (1.f + __expf(-SCALE * sacc[nf][3]));
            dp0 += p00 + p01;
            dp1 += p10 + p11;
            *(uint32_t*)&Pw[g * KSR + c0]       = h2u(__floats2half2_rn(p00, p01));
            *(uint32_t*)&Pw[(g + 8) * KSR + c0] = h2u(__floats2half2_rn(p10, p11));
        }
        __syncwarp();

        // ---- O += P V : 16q x 64d, 32 mmas ----
#pragma unroll
        for (int ks = 0; ks < 4; ++ks) {
            int k0 = ks * 16;
            uint32_t pa[4];
            pa[0] = *(const uint32_t*)&Pw[g * KSR + k0 + 2 * tk];
            pa[1] = *(const uint32_t*)&Pw[(g + 8) * KSR + k0 + 2 * tk];
            pa[2] = *(const uint32_t*)&Pw[g * KSR + k0 + 8 + 2 * tk];
            pa[3] = *(const uint32_t*)&Pw[(g + 8) * KSR + k0 + 8 + 2 * tk];
#pragma unroll
            for (int nf = 0; nf < 8; ++nf) {
                int dn = nf * 8 + g;
                uint32_t bv[2];
                bv[0] = Vtc[dn * VTS + (k0 >> 1) + tk];
                bv[1] = Vtc[dn * VTS + (k0 >> 1) + tk + 4];
                mma_f16(oacc[nf], pa, bv);
            }
        }
        __syncwarp();   // Pw reuse next tile
    }

    // ---- denominators: quad shfl reduction ----
    float d0 = dp0;
    d0 += __shfl_xor_sync(0xFFFFFFFFu, d0, 1);
    d0 += __shfl_xor_sync(0xFFFFFFFFu, d0, 2);
    float d1 = dp1;
    d1 += __shfl_xor_sync(0xFFFFFFFFu, d1, 1);
    d1 += __shfl_xor_sync(0xFFFFFFFFu, d1, 2);
    float inv0 = 1.f / (d0 + EPS);
    float inv1 = 1.f / (d1 + EPS);

    // ---- epilogue: fp16 attention output for the Wo GEMM ----
    __half* Ag = g_A + ((size_t)b * SEQ + qt * AQT) * HID + h * HDIM;
    int row0 = wq + g, row1 = wq + g + 8;
#pragma unroll
    for (int nf = 0; nf < 8; ++nf) {
        int c0 = nf * 8 + 2 * tk;
        *(uint32_t*)&Ag[(size_t)row0 * HID + c0] =
            h2u(__floats2half2_rn(oacc[nf][0] * inv0, oacc[nf][1] * inv0));
        *(uint32_t*)&Ag[(size_t)row1 * HID + c0] =
            h2u(__floats2half2_rn(oacc[nf][2] * inv1, oacc[nf][3] * inv1));
    }
}

// ---------------------------------------------------------------------------
extern "C" void kernel_launch(void* const* d_in, const int* in_sizes, int n_in,
                              void* d_out, int out_size)
{
    __half *Qp, *Kp, *Vp, *Ap, *Xp, *Wp;
    cudaGetSymbolAddress((void**)&Qp, g_Q);
    cudaGetSymbolAddress((void**)&Kp, g_K);
    cudaGetSymbolAddress((void**)&Vp, g_V);
    cudaGetSymbolAddress((void**)&Ap, g_A);
    cudaGetSymbolAddress((void**)&Xp, g_X);
    cudaGetSymbolAddress((void**)&Wp, g_W);

    cudaFuncSetAttribute(attn_f16, cudaFuncAttributeMaxDynamicSharedMemorySize, ASM_TOTAL);

    const float* x  = (const float*)d_in[0];
    const float* Wq = (const float*)d_in[1];
    const float* Wk = (const float*)d_in[2];
    const float* Wv = (const float*)d_in[3];
    const float* Wo = (const float*)d_in[4];
    float* out = (float*)d_out;

    // fp32 -> fp16 conversion
    to_half_k<<<512, 256>>>((const float4*)x,  (uint2*)Xp, MTOT * HID / 4);
    to_half_k<<<256, 256>>>((const float4*)Wq, (uint2*)(Wp + 0 * HID * HID), HID * HID / 4);
    to_half_k<<<256, 256>>>((const float4*)Wk, (uint2*)(Wp + 1 * HID * HID), HID * HID / 4);
    to_half_k<<<256, 256>>>((const float4*)Wv, (uint2*)(Wp + 2 * HID * HID), HID * HID / 4);
    to_half_k<<<256, 256>>>((const float4*)Wo, (uint2*)(Wp + 3 * HID * HID), HID * HID / 4);

    dim3 gemmGrid(HID / 128, MTOT / 128);  // (8, 32)
    gemm_f16<true><<<gemmGrid, 256>>>(Xp, Wp + 0 * HID * HID, Qp, MTOT, HID, HID);
    gemm_f16<true><<<gemmGrid, 256>>>(Xp, Wp + 1 * HID * HID, Kp, MTOT, HID, HID);
    gemm_f16<true><<<gemmGrid, 256>>>(Xp, Wp + 2 * HID * HID, Vp, MTOT, HID, HID);

    dim3 attnGrid(SEQ / AQT, NHEAD, Bsz);  // (8, 16, 2)
    attn_f16<<<attnGrid, 512, ASM_TOTAL>>>();

    gemm_f16<false><<<gemmGrid, 256>>>(Ap, Wp + 3 * HID * HID, out, MTOT, HID, HID);
}

// round 12
// speedup vs baseline: 4.7424x; 1.0391x over previous
#include <cuda_runtime.h>
#include <cuda_fp16.h>
#include <stdint.h>
#include <math.h>

#define Bsz 2
#define SEQ 2048
#define HID 1024
#define NHEAD 16
#define HDIM 64
#define SCALE 0.125f
#define EPS 1e-6f
#define MTOT (Bsz*SEQ)   // 4096

// Scratch (device globals: allocation-free)
__device__ __half g_Q[MTOT * HID];
__device__ __half g_K[MTOT * HID];
__device__ __half g_V[MTOT * HID];
__device__ __half g_A[MTOT * HID];
__device__ __half g_X[MTOT * HID];       // fp16 x
__device__ __half g_W[4 * HID * HID];    // fp16 Wq,Wk,Wv,Wo

// ---------------------------------------------------------------------------
// Helpers
// ---------------------------------------------------------------------------
__device__ __forceinline__ void mma_f16(float* d, const uint32_t* a, const uint32_t* b) {
    asm volatile(
        "mma.sync.aligned.m16n8k16.row.col.f32.f16.f16.f32 "
        "{%0,%1,%2,%3},{%4,%5,%6,%7},{%8,%9},{%0,%1,%2,%3};\n"
        : "+f"(d[0]), "+f"(d[1]), "+f"(d[2]), "+f"(d[3])
        : "r"(a[0]), "r"(a[1]), "r"(a[2]), "r"(a[3]), "r"(b[0]), "r"(b[1]));
}

__device__ __forceinline__ void cp16(void* smem_dst, const void* gmem_src) {
    uint32_t s = (uint32_t)__cvta_generic_to_shared(smem_dst);
    asm volatile("cp.async.cg.shared.global [%0], [%1], 16;\n" :: "r"(s), "l"(gmem_src));
}

__device__ __forceinline__ uint32_t h2u(__half2 h) { return *reinterpret_cast<uint32_t*>(&h); }

// ---------------------------------------------------------------------------
// f32 -> f16 conversion pre-pass
// ---------------------------------------------------------------------------
__global__ void to_half_k(const float4* __restrict__ in, uint2* __restrict__ out, int n4)
{
    for (int i = blockIdx.x * blockDim.x + threadIdx.x; i < n4; i += gridDim.x * blockDim.x) {
        float4 v = in[i];
        out[i] = make_uint2(h2u(__floats2half2_rn(v.x, v.y)),
                            h2u(__floats2half2_rn(v.z, v.w)));
    }
}

// ---------------------------------------------------------------------------
// FP16 GEMM: C[M,N] = A[M,K] * B[N,K]^T   (unchanged from R10 passing kernel)
// ---------------------------------------------------------------------------
#define GS2 72

template<bool HOUT>
__global__ __launch_bounds__(256, 2) void gemm_f16(
    const __half* __restrict__ A, const __half* __restrict__ B,
    void* __restrict__ Cv, int M, int N, int K)
{
    __shared__ __half As[128 * GS2];
    __shared__ __half Bs[128 * GS2];

    const int tid  = threadIdx.x;
    const int lane = tid & 31;
    const int warp = tid >> 5;
    const int g    = lane >> 2;
    const int tk   = lane & 3;
    const int wm   = (warp & 3) * 32;
    const int wn   = (warp >> 2) * 64;
    const int mBase = blockIdx.y * 128;
    const int nBase = blockIdx.x * 128;

    float acc[2][8][4];
#pragma unroll
    for (int mf = 0; mf < 2; ++mf)
#pragma unroll
        for (int nf = 0; nf < 8; ++nf)
#pragma unroll
            for (int i = 0; i < 4; ++i) acc[mf][nf][i] = 0.f;

    const int T = K / 64;
    uint4 fa[4], fb[4];

#pragma unroll
    for (int i = 0; i < 4; ++i) {
        int s = tid + 256 * i, r = s >> 3, c8 = s & 7;
        fa[i] = *(const uint4*)&A[(size_t)(mBase + r) * K + c8 * 8];
        fb[i] = *(const uint4*)&B[(size_t)(nBase + r) * K + c8 * 8];
    }

    for (int t = 0; t < T; ++t) {
        __syncthreads();
#pragma unroll
        for (int i = 0; i < 4; ++i) {
            int s = tid + 256 * i, r = s >> 3, c8 = s & 7;
            *(uint4*)&As[r * GS2 + c8 * 8] = fa[i];
            *(uint4*)&Bs[r * GS2 + c8 * 8] = fb[i];
        }
        __syncthreads();
        if (t + 1 < T) {
            int kOff = (t + 1) * 64;
#pragma unroll
            for (int i = 0; i < 4; ++i) {
                int s = tid + 256 * i, r = s >> 3, c8 = s & 7;
                fa[i] = *(const uint4*)&A[(size_t)(mBase + r) * K + kOff + c8 * 8];
                fb[i] = *(const uint4*)&B[(size_t)(nBase + r) * K + kOff + c8 * 8];
            }
        }
#pragma unroll
        for (int ks = 0; ks < 4; ++ks) {
            int k0 = ks * 16 + 2 * tk;
            uint32_t av[2][4];
#pragma unroll
            for (int mf = 0; mf < 2; ++mf) {
                int r0 = wm + mf * 16 + g;
                av[mf][0] = *(const uint32_t*)&As[r0 * GS2 + k0];
                av[mf][1] = *(const uint32_t*)&As[(r0 + 8) * GS2 + k0];
                av[mf][2] = *(const uint32_t*)&As[r0 * GS2 + k0 + 8];
                av[mf][3] = *(const uint32_t*)&As[(r0 + 8) * GS2 + k0 + 8];
            }
            uint32_t bv[8][2];
#pragma unroll
            for (int nf = 0; nf < 8; ++nf) {
                int rn = wn + nf * 8 + g;
                bv[nf][0] = *(const uint32_t*)&Bs[rn * GS2 + k0];
                bv[nf][1] = *(const uint32_t*)&Bs[rn * GS2 + k0 + 8];
            }
#pragma unroll
            for (int mf = 0; mf < 2; ++mf)
#pragma unroll
                for (int nf = 0; nf < 8; ++nf)
                    mma_f16(acc[mf][nf], av[mf], bv[nf]);
        }
    }

#pragma unroll
    for (int mf = 0; mf < 2; ++mf) {
        int r0 = mBase + wm + mf * 16 + g;
#pragma unroll
        for (int nf = 0; nf < 8; ++nf) {
            int c0 = nBase + wn + nf * 8 + 2 * tk;
            if (HOUT) {
                __half* C = (__half*)Cv;
                *(uint32_t*)&C[(size_t)r0 * N + c0] =
                    h2u(__floats2half2_rn(acc[mf][nf][0], acc[mf][nf][1]));
                *(uint32_t*)&C[(size_t)(r0 + 8) * N + c0] =
                    h2u(__floats2half2_rn(acc[mf][nf][2], acc[mf][nf][3]));
            } else {
                float* C = (float*)Cv;
                *(float2*)&C[(size_t)r0 * N + c0] = make_float2(acc[mf][nf][0], acc[mf][nf][1]);
                *(float2*)&C[(size_t)(r0 + 8) * N + c0] = make_float2(acc[mf][nf][2], acc[mf][nf][3]);
            }
        }
    }
}

// ---------------------------------------------------------------------------
// FP16 sigmoid attention v5 (fixed): P stays in REGISTERS.
// S-accum fragment {c0=rowg kLo, c1.., c2=rowg+8 kLo, c3} packs DIRECTLY into
// the m16n8k16 A-frag order {rowg kLo, rowg+8 kLo, rowg kHi, rowg+8 kHi}
// via pfrag[ks] = { pack(c0,c1)@tile2ks, pack(c2,c3)@tile2ks,
//                   pack(c0,c1)@tile2ks+1, pack(c2,c3)@tile2ks+1 }. No reorder.
// CTA: 256 queries, 512 threads / 16 warps; one CTA barrier per 64-key tile.
// smem: Ks[2] 64x72h | Vt[2] 64x37w  (Q staged over the union at start).
// ---------------------------------------------------------------------------
#define AQT 256
#define ANT 32                    // SEQ / 64
#define KSR 72                    // Ks row stride (halfs)
#define KSBUF (64 * KSR)          // 4608 halfs
#define VTS 37                    // Vt row stride (uint32)
#define VTBUF (64 * VTS)          // 2368 uint32
#define ASM_VT (2 * KSBUF * 2)            // 18432 B
#define ASM_TOTAL (ASM_VT + 2 * VTBUF * 4)  // 37376 B (Q staging needs 36864)

__device__ __forceinline__ void store_vt(uint32_t* Vt, uint2 va, uint2 vb, int d0, int key2)
{
    __half2 a01 = *reinterpret_cast<__half2*>(&va.x);
    __half2 a23 = *reinterpret_cast<__half2*>(&va.y);
    __half2 b01 = *reinterpret_cast<__half2*>(&vb.x);
    __half2 b23 = *reinterpret_cast<__half2*>(&vb.y);
    Vt[(d0 + 0) * VTS + key2] = h2u(__halves2half2(a01.x, b01.x));
    Vt[(d0 + 1) * VTS + key2] = h2u(__halves2half2(a01.y, b01.y));
    Vt[(d0 + 2) * VTS + key2] = h2u(__halves2half2(a23.x, b23.x));
    Vt[(d0 + 3) * VTS + key2] = h2u(__halves2half2(a23.y, b23.y));
}

__global__ __launch_bounds__(512, 1) void attn_f16()
{
    extern __shared__ char smb[];
    __half*   KsBase = (__half*)smb;
    uint32_t* VtBase = (uint32_t*)(smb + ASM_VT);
    __half*   Qs     = (__half*)smb;   // staging overlay (entire smem)

    const int tid  = threadIdx.x;
    const int lane = tid & 31;
    const int warp = tid >> 5;
    const int g    = lane >> 2;
    const int tk   = lane & 3;
    const int wq   = warp * 16;

    const int qt = blockIdx.x, h = blockIdx.y, b = blockIdx.z;
    const __half* Qg = g_Q + ((size_t)b * SEQ + qt * AQT) * HID + h * HDIM;
    const __half* Kg = g_K + (size_t)b * SEQ * HID + h * HDIM;
    const __half* Vg = g_V + (size_t)b * SEQ * HID + h * HDIM;

    // ---- stage Q (256x64 halfs) and extract fragments ----
#pragma unroll
    for (int i = 0; i < 4; ++i) {
        int s = tid + 512 * i, r = s >> 3, c8 = s & 7;
        *(uint4*)&Qs[r * KSR + c8 * 8] = *(const uint4*)&Qg[(size_t)r * HID + c8 * 8];
    }
    __syncthreads();

    uint32_t qa[4][4];
#pragma unroll
    for (int ks = 0; ks < 4; ++ks) {
        int r0 = wq + g, base = ks * 16 + 2 * tk;
        qa[ks][0] = *(const uint32_t*)&Qs[r0 * KSR + base];
        qa[ks][1] = *(const uint32_t*)&Qs[(r0 + 8) * KSR + base];
        qa[ks][2] = *(const uint32_t*)&Qs[r0 * KSR + base + 8];
        qa[ks][3] = *(const uint32_t*)&Qs[(r0 + 8) * KSR + base + 8];
    }
    __syncthreads();   // staging region free before KV prologue

    float oacc[8][4];
#pragma unroll
    for (int nf = 0; nf < 8; ++nf)
#pragma unroll
        for (int i = 0; i < 4; ++i) oacc[nf][i] = 0.f;
    float dp0 = 0.f, dp1 = 0.f;

    // V transpose mapping: thread covers keys (2*vkey2, 2*vkey2+1), dims vd0..vd0+3
    const int vkey2 = tid >> 4;        // 0..31
    const int vd0   = (tid & 15) * 4;  // 0..60
    uint2 va, vb2;

    // ---- prologue: V(0) transposed + K(0) cp.async ----
    {
        const __half* Vr = Vg + (size_t)(2 * vkey2) * HID + vd0;
        va  = *(const uint2*)Vr;
        vb2 = *(const uint2*)(Vr + HID);
        store_vt(VtBase, va, vb2, vd0, vkey2);
        cp16(&KsBase[(tid >> 3) * KSR + (tid & 7) * 8],
             &Kg[(size_t)(tid >> 3) * HID + (tid & 7) * 8]);
        asm volatile("cp.async.commit_group;\n");
    }

    for (int kt = 0; kt < ANT; ++kt) {
        asm volatile("cp.async.wait_group 0;\n" ::: "memory");
        __syncthreads();   // K(kt) ready, Vt[kt&1] complete

        const bool nxt = (kt + 1 < ANT);
        if (nxt) {
            const __half* Vr = Vg + (size_t)((kt + 1) * 64 + 2 * vkey2) * HID + vd0;
            va  = *(const uint2*)Vr;
            vb2 = *(const uint2*)(Vr + HID);
            const __half* Kn = Kg + (size_t)(kt + 1) * 64 * HID;
            cp16(&KsBase[((kt + 1) & 1) * KSBUF + (tid >> 3) * KSR + (tid & 7) * 8],
                 &Kn[(size_t)(tid >> 3) * HID + (tid & 7) * 8]);
            asm volatile("cp.async.commit_group;\n");
        }

        const __half*   Ksc = KsBase + (kt & 1) * KSBUF;
        const uint32_t* Vtc = VtBase + (kt & 1) * VTBUF;

        // ---- S = Q K^T : 16q x 64k, 32 mmas ----
        float sacc[8][4];
#pragma unroll
        for (int nf = 0; nf < 8; ++nf)
#pragma unroll
            for (int i = 0; i < 4; ++i) sacc[nf][i] = 0.f;
#pragma unroll
        for (int nf = 0; nf < 8; ++nf) {
            int rn = nf * 8 + g;
#pragma unroll
            for (int ks = 0; ks < 4; ++ks) {
                int k0 = ks * 16 + 2 * tk;
                uint32_t bv[2];
                bv[0] = *(const uint32_t*)&Ksc[rn * KSR + k0];
                bv[1] = *(const uint32_t*)&Ksc[rn * KSR + k0 + 8];
                mma_f16(sacc[nf], qa[ks], bv);
            }
        }

        // stash V(kt+1) transposed into the other buffer (ordered by next barrier)
        if (nxt) store_vt(VtBase + ((kt + 1) & 1) * VTBUF, va, vb2, vd0, vkey2);

        // ---- P = sigmoid(scale*S) in REGISTERS; pack straight to A-frags ----
        // S-tile 2ks supplies k-cols 0-7 of PV mma ks; tile 2ks+1 supplies 8-15.
        // pack(c0,c1) = rowg pair, pack(c2,c3) = rowg+8 pair -> A-frag order
        // {rowg kLo, rowg+8 kLo, rowg kHi, rowg+8 kHi} with NO reordering.
        uint32_t pfrag[4][4];
#pragma unroll
        for (int ks = 0; ks < 4; ++ks) {
#pragma unroll
            for (int half8 = 0; half8 < 2; ++half8) {
                const float* s4 = sacc[2 * ks + half8];
                float p00 = 1.f / (1.f + __expf(-SCALE * s4[0]));
                float p01 = 1.f / (1.f + __expf(-SCALE * s4[1]));
                float p10 = 1.f / (1.f + __expf(-SCALE * s4[2]));
                float p11 = 1.f / (1.f + __expf(-SCALE * s4[3]));
                dp0 += p00 + p01;
                dp1 += p10 + p11;
                pfrag[ks][half8 * 2 + 0] = h2u(__floats2half2_rn(p00, p01));  // rowg
                pfrag[ks][half8 * 2 + 1] = h2u(__floats2half2_rn(p10, p11));  // rowg+8
            }
        }

        // ---- O += P V : 16q x 64d, 32 mmas (A from registers) ----
#pragma unroll
        for (int ks = 0; ks < 4; ++ks) {
            int k0 = ks * 16;
#pragma unroll
            for (int nf = 0; nf < 8; ++nf) {
                int dn = nf * 8 + g;
                uint32_t bv[2];
                bv[0] = Vtc[dn * VTS + (k0 >> 1) + tk];
                bv[1] = Vtc[dn * VTS + (k0 >> 1) + tk + 4];
                mma_f16(oacc[nf], pfrag[ks], bv);
            }
        }
    }

    // ---- denominators: quad shfl reduction ----
    float d0 = dp0;
    d0 += __shfl_xor_sync(0xFFFFFFFFu, d0, 1);
    d0 += __shfl_xor_sync(0xFFFFFFFFu, d0, 2);
    float d1 = dp1;
    d1 += __shfl_xor_sync(0xFFFFFFFFu, d1, 1);
    d1 += __shfl_xor_sync(0xFFFFFFFFu, d1, 2);
    float inv0 = 1.f / (d0 + EPS);
    float inv1 = 1.f / (d1 + EPS);

    // ---- epilogue: fp16 attention output for the Wo GEMM ----
    __half* Ag = g_A + ((size_t)b * SEQ + qt * AQT) * HID + h * HDIM;
    int row0 = wq + g, row1 = wq + g + 8;
#pragma unroll
    for (int nf = 0; nf < 8; ++nf) {
        int c0 = nf * 8 + 2 * tk;
        *(uint32_t*)&Ag[(size_t)row0 * HID + c0] =
            h2u(__floats2half2_rn(oacc[nf][0] * inv0, oacc[nf][1] * inv0));
        *(uint32_t*)&Ag[(size_t)row1 * HID + c0] =
            h2u(__floats2half2_rn(oacc[nf][2] * inv1, oacc[nf][3] * inv1));
    }
}

// ---------------------------------------------------------------------------
extern "C" void kernel_launch(void* const* d_in, const int* in_sizes, int n_in,
                              void* d_out, int out_size)
{
    __half *Qp, *Kp, *Vp, *Ap, *Xp, *Wp;
    cudaGetSymbolAddress((void**)&Qp, g_Q);
    cudaGetSymbolAddress((void**)&Kp, g_K);
    cudaGetSymbolAddress((void**)&Vp, g_V);
    cudaGetSymbolAddress((void**)&Ap, g_A);
    cudaGetSymbolAddress((void**)&Xp, g_X);
    cudaGetSymbolAddress((void**)&Wp, g_W);

    cudaFuncSetAttribute(attn_f16, cudaFuncAttributeMaxDynamicSharedMemorySize, ASM_TOTAL);

    const float* x  = (const float*)d_in[0];
    const float* Wq = (const float*)d_in[1];
    const float* Wk = (const float*)d_in[2];
    const float* Wv = (const float*)d_in[3];
    const float* Wo = (const float*)d_in[4];
    float* out = (float*)d_out;

    // fp32 -> fp16 conversion
    to_half_k<<<512, 256>>>((const float4*)x,  (uint2*)Xp, MTOT * HID / 4);
    to_half_k<<<256, 256>>>((const float4*)Wq, (uint2*)(Wp + 0 * HID * HID), HID * HID / 4);
    to_half_k<<<256, 256>>>((const float4*)Wk, (uint2*)(Wp + 1 * HID * HID), HID * HID / 4);
    to_half_k<<<256, 256>>>((const float4*)Wv, (uint2*)(Wp + 2 * HID * HID), HID * HID / 4);
    to_half_k<<<256, 256>>>((const float4*)Wo, (uint2*)(Wp + 3 * HID * HID), HID * HID / 4);

    dim3 gemmGrid(HID / 128, MTOT / 128);  // (8, 32)
    gemm_f16<true><<<gemmGrid, 256>>>(Xp, Wp + 0 * HID * HID, Qp, MTOT, HID, HID);
    gemm_f16<true><<<gemmGrid, 256>>>(Xp, Wp + 1 * HID * HID, Kp, MTOT, HID, HID);
    gemm_f16<true><<<gemmGrid, 256>>>(Xp, Wp + 2 * HID * HID, Vp, MTOT, HID, HID);

    dim3 attnGrid(SEQ / AQT, NHEAD, Bsz);  // (8, 16, 2)
    attn_f16<<<attnGrid, 512, ASM_TOTAL>>>();

    gemm_f16<false><<<gemmGrid, 256>>>(Ap, Wp + 3 * HID * HID, out, MTOT, HID, HID);
}

// round 13
// speedup vs baseline: 4.8913x; 1.0314x over previous
#include <cuda_runtime.h>
#include <cuda_fp16.h>
#include <stdint.h>
#include <math.h>

#define Bsz 2
#define SEQ 2048
#define HID 1024
#define NHEAD 16
#define HDIM 64
#define SCALE 0.125f
#define EPS 1e-6f
#define MTOT (Bsz*SEQ)   // 4096
#define STR3 (3*HID)     // fused QKV row stride

// Scratch (device globals: allocation-free)
__device__ __half g_QKV[MTOT * STR3];    // fused Q|K|V projections
__device__ __half g_A[MTOT * HID];
__device__ __half g_X[MTOT * HID];       // fp16 x
__device__ __half g_W[4 * HID * HID];    // fp16 Wq,Wk,Wv,Wo (contiguous)

// ---------------------------------------------------------------------------
// Helpers
// ---------------------------------------------------------------------------
__device__ __forceinline__ void mma_f16(float* d, const uint32_t* a, const uint32_t* b) {
    asm volatile(
        "mma.sync.aligned.m16n8k16.row.col.f32.f16.f16.f32 "
        "{%0,%1,%2,%3},{%4,%5,%6,%7},{%8,%9},{%0,%1,%2,%3};\n"
        : "+f"(d[0]), "+f"(d[1]), "+f"(d[2]), "+f"(d[3])
        : "r"(a[0]), "r"(a[1]), "r"(a[2]), "r"(a[3]), "r"(b[0]), "r"(b[1]));
}

__device__ __forceinline__ void cp16(void* smem_dst, const void* gmem_src) {
    uint32_t s = (uint32_t)__cvta_generic_to_shared(smem_dst);
    asm volatile("cp.async.cg.shared.global [%0], [%1], 16;\n" :: "r"(s), "l"(gmem_src));
}

__device__ __forceinline__ uint32_t h2u(__half2 h) { return *reinterpret_cast<uint32_t*>(&h); }

// ---------------------------------------------------------------------------
// f32 -> f16 conversion pre-passes
// ---------------------------------------------------------------------------
__global__ void to_half_k(const float4* __restrict__ in, uint2* __restrict__ out, int n4)
{
    for (int i = blockIdx.x * blockDim.x + threadIdx.x; i < n4; i += gridDim.x * blockDim.x) {
        float4 v = in[i];
        out[i] = make_uint2(h2u(__floats2half2_rn(v.x, v.y)),
                            h2u(__floats2half2_rn(v.z, v.w)));
    }
}

// all 4 weights in one launch: segment s = i>>18 (HID*HID/4 = 2^18 float4s)
__global__ void to_half_w4(const float4* __restrict__ w0, const float4* __restrict__ w1,
                           const float4* __restrict__ w2, const float4* __restrict__ w3,
                           uint2* __restrict__ out)
{
    const int n4 = HID * HID / 4;                   // 262144 = 1<<18
    const int total = 4 * n4;
    for (int i = blockIdx.x * blockDim.x + threadIdx.x; i < total; i += gridDim.x * blockDim.x) {
        int seg = i >> 18, off = i & (n4 - 1);
        const float4* src = (seg == 0) ? w0 : (seg == 1) ? w1 : (seg == 2) ? w2 : w3;
        float4 v = src[off];
        out[i] = make_uint2(h2u(__floats2half2_rn(v.x, v.y)),
                            h2u(__floats2half2_rn(v.z, v.w)));
    }
}

// ---------------------------------------------------------------------------
// FP16 GEMM: C[M,N] = A[M,K] * B[N,K]^T   (N is also the C row stride)
// CTA tile 128x128, BK=64 halfs, 8 warps, warp tile 32x64. Register-prefetch.
// ---------------------------------------------------------------------------
#define GS2 72

template<bool HOUT>
__global__ __launch_bounds__(256, 2) void gemm_f16(
    const __half* __restrict__ A, const __half* __restrict__ B,
    void* __restrict__ Cv, int M, int N, int K)
{
    __shared__ __half As[128 * GS2];
    __shared__ __half Bs[128 * GS2];

    const int tid  = threadIdx.x;
    const int lane = tid & 31;
    const int warp = tid >> 5;
    const int g    = lane >> 2;
    const int tk   = lane & 3;
    const int wm   = (warp & 3) * 32;
    const int wn   = (warp >> 2) * 64;
    const int mBase = blockIdx.y * 128;
    const int nBase = blockIdx.x * 128;

    float acc[2][8][4];
#pragma unroll
    for (int mf = 0; mf < 2; ++mf)
#pragma unroll
        for (int nf = 0; nf < 8; ++nf)
#pragma unroll
            for (int i = 0; i < 4; ++i) acc[mf][nf][i] = 0.f;

    const int T = K / 64;
    uint4 fa[4], fb[4];

#pragma unroll
    for (int i = 0; i < 4; ++i) {
        int s = tid + 256 * i, r = s >> 3, c8 = s & 7;
        fa[i] = *(const uint4*)&A[(size_t)(mBase + r) * K + c8 * 8];
        fb[i] = *(const uint4*)&B[(size_t)(nBase + r) * K + c8 * 8];
    }

    for (int t = 0; t < T; ++t) {
        __syncthreads();
#pragma unroll
        for (int i = 0; i < 4; ++i) {
            int s = tid + 256 * i, r = s >> 3, c8 = s & 7;
            *(uint4*)&As[r * GS2 + c8 * 8] = fa[i];
            *(uint4*)&Bs[r * GS2 + c8 * 8] = fb[i];
        }
        __syncthreads();
        if (t + 1 < T) {
            int kOff = (t + 1) * 64;
#pragma unroll
            for (int i = 0; i < 4; ++i) {
                int s = tid + 256 * i, r = s >> 3, c8 = s & 7;
                fa[i] = *(const uint4*)&A[(size_t)(mBase + r) * K + kOff + c8 * 8];
                fb[i] = *(const uint4*)&B[(size_t)(nBase + r) * K + kOff + c8 * 8];
            }
        }
#pragma unroll
        for (int ks = 0; ks < 4; ++ks) {
            int k0 = ks * 16 + 2 * tk;
            uint32_t av[2][4];
#pragma unroll
            for (int mf = 0; mf < 2; ++mf) {
                int r0 = wm + mf * 16 + g;
                av[mf][0] = *(const uint32_t*)&As[r0 * GS2 + k0];
                av[mf][1] = *(const uint32_t*)&As[(r0 + 8) * GS2 + k0];
                av[mf][2] = *(const uint32_t*)&As[r0 * GS2 + k0 + 8];
                av[mf][3] = *(const uint32_t*)&As[(r0 + 8) * GS2 + k0 + 8];
            }
            uint32_t bv[8][2];
#pragma unroll
            for (int nf = 0; nf < 8; ++nf) {
                int rn = wn + nf * 8 + g;
                bv[nf][0] = *(const uint32_t*)&Bs[rn * GS2 + k0];
                bv[nf][1] = *(const uint32_t*)&Bs[rn * GS2 + k0 + 8];
            }
#pragma unroll
            for (int mf = 0; mf < 2; ++mf)
#pragma unroll
                for (int nf = 0; nf < 8; ++nf)
                    mma_f16(acc[mf][nf], av[mf], bv[nf]);
        }
    }

#pragma unroll
    for (int mf = 0; mf < 2; ++mf) {
        int r0 = mBase + wm + mf * 16 + g;
#pragma unroll
        for (int nf = 0; nf < 8; ++nf) {
            int c0 = nBase + wn + nf * 8 + 2 * tk;
            if (HOUT) {
                __half* C = (__half*)Cv;
                *(uint32_t*)&C[(size_t)r0 * N + c0] =
                    h2u(__floats2half2_rn(acc[mf][nf][0], acc[mf][nf][1]));
                *(uint32_t*)&C[(size_t)(r0 + 8) * N + c0] =
                    h2u(__floats2half2_rn(acc[mf][nf][2], acc[mf][nf][3]));
            } else {
                float* C = (float*)Cv;
                *(float2*)&C[(size_t)r0 * N + c0] = make_float2(acc[mf][nf][0], acc[mf][nf][1]);
                *(float2*)&C[(size_t)(r0 + 8) * N + c0] = make_float2(acc[mf][nf][2], acc[mf][nf][3]);
            }
        }
    }
}

// ---------------------------------------------------------------------------
// FP16 sigmoid attention v5 (P in registers), reading fused QKV (stride 3H).
// CTA: 256 queries, 512 threads / 16 warps; one CTA barrier per 64-key tile.
// smem: Ks[2] 64x72h | Vt[2] 64x37w  (Q staged over the union at start).
// ---------------------------------------------------------------------------
#define AQT 256
#define ANT 32                    // SEQ / 64
#define KSR 72                    // Ks row stride (halfs)
#define KSBUF (64 * KSR)          // 4608 halfs
#define VTS 37                    // Vt row stride (uint32)
#define VTBUF (64 * VTS)          // 2368 uint32
#define ASM_VT (2 * KSBUF * 2)            // 18432 B
#define ASM_TOTAL (ASM_VT + 2 * VTBUF * 4)  // 37376 B

__device__ __forceinline__ void store_vt(uint32_t* Vt, uint2 va, uint2 vb, int d0, int key2)
{
    __half2 a01 = *reinterpret_cast<__half2*>(&va.x);
    __half2 a23 = *reinterpret_cast<__half2*>(&va.y);
    __half2 b01 = *reinterpret_cast<__half2*>(&vb.x);
    __half2 b23 = *reinterpret_cast<__half2*>(&vb.y);
    Vt[(d0 + 0) * VTS + key2] = h2u(__halves2half2(a01.x, b01.x));
    Vt[(d0 + 1) * VTS + key2] = h2u(__halves2half2(a01.y, b01.y));
    Vt[(d0 + 2) * VTS + key2] = h2u(__halves2half2(a23.x, b23.x));
    Vt[(d0 + 3) * VTS + key2] = h2u(__halves2half2(a23.y, b23.y));
}

__global__ __launch_bounds__(512, 1) void attn_f16()
{
    extern __shared__ char smb[];
    __half*   KsBase = (__half*)smb;
    uint32_t* VtBase = (uint32_t*)(smb + ASM_VT);
    __half*   Qs     = (__half*)smb;   // staging overlay (entire smem)

    const int tid  = threadIdx.x;
    const int lane = tid & 31;
    const int warp = tid >> 5;
    const int g    = lane >> 2;
    const int tk   = lane & 3;
    const int wq   = warp * 16;

    const int qt = blockIdx.x, h = blockIdx.y, b = blockIdx.z;
    const __half* Qg = g_QKV + ((size_t)b * SEQ + qt * AQT) * STR3 + h * HDIM;
    const __half* Kg = g_QKV + (size_t)b * SEQ * STR3 + HID + h * HDIM;
    const __half* Vg = g_QKV + (size_t)b * SEQ * STR3 + 2 * HID + h * HDIM;

    // ---- stage Q (256x64 halfs) and extract fragments ----
#pragma unroll
    for (int i = 0; i < 4; ++i) {
        int s = tid + 512 * i, r = s >> 3, c8 = s & 7;
        *(uint4*)&Qs[r * KSR + c8 * 8] = *(const uint4*)&Qg[(size_t)r * STR3 + c8 * 8];
    }
    __syncthreads();

    uint32_t qa[4][4];
#pragma unroll
    for (int ks = 0; ks < 4; ++ks) {
        int r0 = wq + g, base = ks * 16 + 2 * tk;
        qa[ks][0] = *(const uint32_t*)&Qs[r0 * KSR + base];
        qa[ks][1] = *(const uint32_t*)&Qs[(r0 + 8) * KSR + base];
        qa[ks][2] = *(const uint32_t*)&Qs[r0 * KSR + base + 8];
        qa[ks][3] = *(const uint32_t*)&Qs[(r0 + 8) * KSR + base + 8];
    }
    __syncthreads();   // staging region free before KV prologue

    float oacc[8][4];
#pragma unroll
    for (int nf = 0; nf < 8; ++nf)
#pragma unroll
        for (int i = 0; i < 4; ++i) oacc[nf][i] = 0.f;
    float dp0 = 0.f, dp1 = 0.f;

    // V transpose mapping: thread covers keys (2*vkey2, 2*vkey2+1), dims vd0..vd0+3
    const int vkey2 = tid >> 4;        // 0..31
    const int vd0   = (tid & 15) * 4;  // 0..60
    uint2 va, vb2;

    // ---- prologue: V(0) transposed + K(0) cp.async ----
    {
        const __half* Vr = Vg + (size_t)(2 * vkey2) * STR3 + vd0;
        va  = *(const uint2*)Vr;
        vb2 = *(const uint2*)(Vr + STR3);
        store_vt(VtBase, va, vb2, vd0, vkey2);
        cp16(&KsBase[(tid >> 3) * KSR + (tid & 7) * 8],
             &Kg[(size_t)(tid >> 3) * STR3 + (tid & 7) * 8]);
        asm volatile("cp.async.commit_group;\n");
    }

    for (int kt = 0; kt < ANT; ++kt) {
        asm volatile("cp.async.wait_group 0;\n" ::: "memory");
        __syncthreads();   // K(kt) ready, Vt[kt&1] complete

        const bool nxt = (kt + 1 < ANT);
        if (nxt) {
            const __half* Vr = Vg + (size_t)((kt + 1) * 64 + 2 * vkey2) * STR3 + vd0;
            va  = *(const uint2*)Vr;
            vb2 = *(const uint2*)(Vr + STR3);
            const __half* Kn = Kg + (size_t)(kt + 1) * 64 * STR3;
            cp16(&KsBase[((kt + 1) & 1) * KSBUF + (tid >> 3) * KSR + (tid & 7) * 8],
                 &Kn[(size_t)(tid >> 3) * STR3 + (tid & 7) * 8]);
            asm volatile("cp.async.commit_group;\n");
        }

        const __half*   Ksc = KsBase + (kt & 1) * KSBUF;
        const uint32_t* Vtc = VtBase + (kt & 1) * VTBUF;

        // ---- S = Q K^T : 16q x 64k, 32 mmas ----
        float sacc[8][4];
#pragma unroll
        for (int nf = 0; nf < 8; ++nf)
#pragma unroll
            for (int i = 0; i < 4; ++i) sacc[nf][i] = 0.f;
#pragma unroll
        for (int nf = 0; nf < 8; ++nf) {
            int rn = nf * 8 + g;
#pragma unroll
            for (int ks = 0; ks < 4; ++ks) {
                int k0 = ks * 16 + 2 * tk;
                uint32_t bv[2];
                bv[0] = *(const uint32_t*)&Ksc[rn * KSR + k0];
                bv[1] = *(const uint32_t*)&Ksc[rn * KSR + k0 + 8];
                mma_f16(sacc[nf], qa[ks], bv);
            }
        }

        // stash V(kt+1) transposed into the other buffer (ordered by next barrier)
        if (nxt) store_vt(VtBase + ((kt + 1) & 1) * VTBUF, va, vb2, vd0, vkey2);

        // ---- P = sigmoid(scale*S) in REGISTERS; pack straight to A-frags ----
        uint32_t pfrag[4][4];
#pragma unroll
        for (int ks = 0; ks < 4; ++ks) {
#pragma unroll
            for (int half8 = 0; half8 < 2; ++half8) {
                const float* s4 = sacc[2 * ks + half8];
                float p00 = 1.f / (1.f + __expf(-SCALE * s4[0]));
                float p01 = 1.f / (1.f + __expf(-SCALE * s4[1]));
                float p10 = 1.f / (1.f + __expf(-SCALE * s4[2]));
                float p11 = 1.f / (1.f + __expf(-SCALE * s4[3]));
                dp0 += p00 + p01;
                dp1 += p10 + p11;
                pfrag[ks][half8 * 2 + 0] = h2u(__floats2half2_rn(p00, p01));  // rowg
                pfrag[ks][half8 * 2 + 1] = h2u(__floats2half2_rn(p10, p11));  // rowg+8
            }
        }

        // ---- O += P V : 16q x 64d, 32 mmas (A from registers) ----
#pragma unroll
        for (int ks = 0; ks < 4; ++ks) {
            int k0 = ks * 16;
#pragma unroll
            for (int nf = 0; nf < 8; ++nf) {
                int dn = nf * 8 + g;
                uint32_t bv[2];
                bv[0] = Vtc[dn * VTS + (k0 >> 1) + tk];
                bv[1] = Vtc[dn * VTS + (k0 >> 1) + tk + 4];
                mma_f16(oacc[nf], pfrag[ks], bv);
            }
        }
    }

    // ---- denominators: quad shfl reduction ----
    float d0 = dp0;
    d0 += __shfl_xor_sync(0xFFFFFFFFu, d0, 1);
    d0 += __shfl_xor_sync(0xFFFFFFFFu, d0, 2);
    float d1 = dp1;
    d1 += __shfl_xor_sync(0xFFFFFFFFu, d1, 1);
    d1 += __shfl_xor_sync(0xFFFFFFFFu, d1, 2);
    float inv0 = 1.f / (d0 + EPS);
    float inv1 = 1.f / (d1 + EPS);

    // ---- epilogue: fp16 attention output for the Wo GEMM ----
    __half* Ag = g_A + ((size_t)b * SEQ + qt * AQT) * HID + h * HDIM;
    int row0 = wq + g, row1 = wq + g + 8;
#pragma unroll
    for (int nf = 0; nf < 8; ++nf) {
        int c0 = nf * 8 + 2 * tk;
        *(uint32_t*)&Ag[(size_t)row0 * HID + c0] =
            h2u(__floats2half2_rn(oacc[nf][0] * inv0, oacc[nf][1] * inv0));
        *(uint32_t*)&Ag[(size_t)row1 * HID + c0] =
            h2u(__floats2half2_rn(oacc[nf][2] * inv1, oacc[nf][3] * inv1));
    }
}

// ---------------------------------------------------------------------------
extern "C" void kernel_launch(void* const* d_in, const int* in_sizes, int n_in,
                              void* d_out, int out_size)
{
    __half *QKVp, *Ap, *Xp, *Wp;
    cudaGetSymbolAddress((void**)&QKVp, g_QKV);
    cudaGetSymbolAddress((void**)&Ap, g_A);
    cudaGetSymbolAddress((void**)&Xp, g_X);
    cudaGetSymbolAddress((void**)&Wp, g_W);

    cudaFuncSetAttribute(attn_f16, cudaFuncAttributeMaxDynamicSharedMemorySize, ASM_TOTAL);

    const float* x  = (const float*)d_in[0];
    const float* Wq = (const float*)d_in[1];
    const float* Wk = (const float*)d_in[2];
    const float* Wv = (const float*)d_in[3];
    const float* Wo = (const float*)d_in[4];
    float* out = (float*)d_out;

    // fp32 -> fp16 conversions (2 launches)
    to_half_k<<<512, 256>>>((const float4*)x, (uint2*)Xp, MTOT * HID / 4);
    to_half_w4<<<512, 256>>>((const float4*)Wq, (const float4*)Wk,
                             (const float4*)Wv, (const float4*)Wo, (uint2*)Wp);

    // fused QKV projection: C[4096, 3072] = X @ [Wq;Wk;Wv]^T
    dim3 qkvGrid(STR3 / 128, MTOT / 128);  // (24, 32) = 768 CTAs
    gemm_f16<true><<<qkvGrid, 256>>>(Xp, Wp, QKVp, MTOT, STR3, HID);

    dim3 attnGrid(SEQ / AQT, NHEAD, Bsz);  // (8, 16, 2)
    attn_f16<<<attnGrid, 512, ASM_TOTAL>>>();

    dim3 oGrid(HID / 128, MTOT / 128);     // (8, 32)
    gemm_f16<false><<<oGrid, 256>>>(Ap, Wp + 3 * HID * HID, out, MTOT, HID, HID);
}

// round 15
// speedup vs baseline: 6.8607x; 1.4027x over previous
#include <cuda_runtime.h>
#include <cuda_fp16.h>
#include <stdint.h>
#include <math.h>

#define Bsz 2
#define SEQ 2048
#define HID 1024
#define NHEAD 16
#define HDIM 64
#define SCALE 0.125f
#define EPS 1e-6f
#define MTOT (Bsz*SEQ)   // 4096
#define STR3 (3*HID)     // fused QKV row stride

// Scratch (device globals: allocation-free)
__device__ __half g_QKV[MTOT * STR3];    // fused Q|K|V projections
__device__ __half g_A[MTOT * HID];
__device__ __half g_X[MTOT * HID];       // fp16 x
__device__ __half g_W[4 * HID * HID];    // fp16 Wq,Wk,Wv,Wo (contiguous)

// ---------------------------------------------------------------------------
// Helpers
// ---------------------------------------------------------------------------
__device__ __forceinline__ void mma_f16(float* d, const uint32_t* a, const uint32_t* b) {
    asm volatile(
        "mma.sync.aligned.m16n8k16.row.col.f32.f16.f16.f32 "
        "{%0,%1,%2,%3},{%4,%5,%6,%7},{%8,%9},{%0,%1,%2,%3};\n"
        : "+f"(d[0]), "+f"(d[1]), "+f"(d[2]), "+f"(d[3])
        : "r"(a[0]), "r"(a[1]), "r"(a[2]), "r"(a[3]), "r"(b[0]), "r"(b[1]));
}

__device__ __forceinline__ void ldsm_x4(uint32_t& r0, uint32_t& r1, uint32_t& r2,
                                        uint32_t& r3, uint32_t addr) {
    asm volatile("ldmatrix.sync.aligned.m8n8.x4.shared.b16 {%0,%1,%2,%3}, [%4];"
                 : "=r"(r0), "=r"(r1), "=r"(r2), "=r"(r3) : "r"(addr));
}

__device__ __forceinline__ void cp16(void* smem_dst, const void* gmem_src) {
    uint32_t s = (uint32_t)__cvta_generic_to_shared(smem_dst);
    asm volatile("cp.async.cg.shared.global [%0], [%1], 16;\n" :: "r"(s), "l"(gmem_src));
}

__device__ __forceinline__ uint32_t h2u(__half2 h) { return *reinterpret_cast<uint32_t*>(&h); }

// ---------------------------------------------------------------------------
// f32 -> f16 conversion pre-passes
// ---------------------------------------------------------------------------
__global__ void to_half_k(const float4* __restrict__ in, uint2* __restrict__ out, int n4)
{
    for (int i = blockIdx.x * blockDim.x + threadIdx.x; i < n4; i += gridDim.x * blockDim.x) {
        float4 v = in[i];
        out[i] = make_uint2(h2u(__floats2half2_rn(v.x, v.y)),
                            h2u(__floats2half2_rn(v.z, v.w)));
    }
}

__global__ void to_half_w4(const float4* __restrict__ w0, const float4* __restrict__ w1,
                           const float4* __restrict__ w2, const float4* __restrict__ w3,
                           uint2* __restrict__ out)
{
    const int n4 = HID * HID / 4;                   // 1<<18
    const int total = 4 * n4;
    for (int i = blockIdx.x * blockDim.x + threadIdx.x; i < total; i += gridDim.x * blockDim.x) {
        int seg = i >> 18, off = i & (n4 - 1);
        const float4* src = (seg == 0) ? w0 : (seg == 1) ? w1 : (seg == 2) ? w2 : w3;
        float4 v = src[off];
        out[i] = make_uint2(h2u(__floats2half2_rn(v.x, v.y)),
                            h2u(__floats2half2_rn(v.z, v.w)));
    }
}

// ---------------------------------------------------------------------------
// FP16 GEMM (unchanged from R13 passing kernel)
// ---------------------------------------------------------------------------
#define GS2 72

template<bool HOUT>
__global__ __launch_bounds__(256, 2) void gemm_f16(
    const __half* __restrict__ A, const __half* __restrict__ B,
    void* __restrict__ Cv, int M, int N, int K)
{
    __shared__ __half As[128 * GS2];
    __shared__ __half Bs[128 * GS2];

    const int tid  = threadIdx.x;
    const int lane = tid & 31;
    const int warp = tid >> 5;
    const int g    = lane >> 2;
    const int tk   = lane & 3;
    const int wm   = (warp & 3) * 32;
    const int wn   = (warp >> 2) * 64;
    const int mBase = blockIdx.y * 128;
    const int nBase = blockIdx.x * 128;

    float acc[2][8][4];
#pragma unroll
    for (int mf = 0; mf < 2; ++mf)
#pragma unroll
        for (int nf = 0; nf < 8; ++nf)
#pragma unroll
            for (int i = 0; i < 4; ++i) acc[mf][nf][i] = 0.f;

    const int T = K / 64;
    uint4 fa[4], fb[4];

#pragma unroll
    for (int i = 0; i < 4; ++i) {
        int s = tid + 256 * i, r = s >> 3, c8 = s & 7;
        fa[i] = *(const uint4*)&A[(size_t)(mBase + r) * K + c8 * 8];
        fb[i] = *(const uint4*)&B[(size_t)(nBase + r) * K + c8 * 8];
    }

    for (int t = 0; t < T; ++t) {
        __syncthreads();
#pragma unroll
        for (int i = 0; i < 4; ++i) {
            int s = tid + 256 * i, r = s >> 3, c8 = s & 7;
            *(uint4*)&As[r * GS2 + c8 * 8] = fa[i];
            *(uint4*)&Bs[r * GS2 + c8 * 8] = fb[i];
        }
        __syncthreads();
        if (t + 1 < T) {
            int kOff = (t + 1) * 64;
#pragma unroll
            for (int i = 0; i < 4; ++i) {
                int s = tid + 256 * i, r = s >> 3, c8 = s & 7;
                fa[i] = *(const uint4*)&A[(size_t)(mBase + r) * K + kOff + c8 * 8];
                fb[i] = *(const uint4*)&B[(size_t)(nBase + r) * K + kOff + c8 * 8];
            }
        }
#pragma unroll
        for (int ks = 0; ks < 4; ++ks) {
            int k0 = ks * 16 + 2 * tk;
            uint32_t av[2][4];
#pragma unroll
            for (int mf = 0; mf < 2; ++mf) {
                int r0 = wm + mf * 16 + g;
                av[mf][0] = *(const uint32_t*)&As[r0 * GS2 + k0];
                av[mf][1] = *(const uint32_t*)&As[(r0 + 8) * GS2 + k0];
                av[mf][2] = *(const uint32_t*)&As[r0 * GS2 + k0 + 8];
                av[mf][3] = *(const uint32_t*)&As[(r0 + 8) * GS2 + k0 + 8];
            }
            uint32_t bv[8][2];
#pragma unroll
            for (int nf = 0; nf < 8; ++nf) {
                int rn = wn + nf * 8 + g;
                bv[nf][0] = *(const uint32_t*)&Bs[rn * GS2 + k0];
                bv[nf][1] = *(const uint32_t*)&Bs[rn * GS2 + k0 + 8];
            }
#pragma unroll
            for (int mf = 0; mf < 2; ++mf)
#pragma unroll
                for (int nf = 0; nf < 8; ++nf)
                    mma_f16(acc[mf][nf], av[mf], bv[nf]);
        }
    }

#pragma unroll
    for (int mf = 0; mf < 2; ++mf) {
        int r0 = mBase + wm + mf * 16 + g;
#pragma unroll
        for (int nf = 0; nf < 8; ++nf) {
            int c0 = nBase + wn + nf * 8 + 2 * tk;
            if (HOUT) {
                __half* C = (__half*)Cv;
                *(uint32_t*)&C[(size_t)r0 * N + c0] =
                    h2u(__floats2half2_rn(acc[mf][nf][0], acc[mf][nf][1]));
                *(uint32_t*)&C[(size_t)(r0 + 8) * N + c0] =
                    h2u(__floats2half2_rn(acc[mf][nf][2], acc[mf][nf][3]));
            } else {
                float* C = (float*)Cv;
                *(float2*)&C[(size_t)r0 * N + c0] = make_float2(acc[mf][nf][0], acc[mf][nf][1]);
                *(float2*)&C[(size_t)(r0 + 8) * N + c0] = make_float2(acc[mf][nf][2], acc[mf][nf][3]);
            }
        }
    }
}

// ---------------------------------------------------------------------------
// FP16 sigmoid attention v6: ldmatrix fragment loads, K-tile 128 (2 subtiles
// per CTA barrier), P in registers, __fdividef sigmoid.
// CTA: 256 queries, 512 threads / 16 warps; warp w owns q-rows [16w,16w+16).
// smem: Ks[2] 128x72h (144B rows) | Vt[2] 64x68w (272B rows).
// ---------------------------------------------------------------------------
#define AQT 256
#define KT2 16                    // SEQ / 128
#define KSR 72                    // Ks row stride (halfs) = 144 B
#define KSBYTES (128 * 144)       // 18432 B per K buffer
#define VTS 68                    // Vt row stride (uint32) = 272 B
#define VTBYTES (64 * 272)        // 17408 B per V buffer
#define ASM_VT (2 * KSBYTES)      // 36864
#define ASM_TOTAL (ASM_VT + 2 * VTBYTES)   // 71680 B

// store 8 dims x 2 keys transposed into Vt
__device__ __forceinline__ void store_vt8(uint32_t* Vt, uint4 A, uint4 B, int vm, int key2)
{
    const __half2* a = (const __half2*)&A;
    const __half2* bb = (const __half2*)&B;
#pragma unroll
    for (int j = 0; j < 4; ++j) {
        __half2 aj = a[j], bj = bb[j];
        Vt[(vm * 8 + 2 * j)     * VTS + key2] = h2u(__halves2half2(aj.x, bj.x));
        Vt[(vm * 8 + 2 * j + 1) * VTS + key2] = h2u(__halves2half2(aj.y, bj.y));
    }
}

__global__ __launch_bounds__(512, 1) void attn_f16()
{
    extern __shared__ char smb[];
    __half*   KsBase = (__half*)smb;
    uint32_t* VtBase = (uint32_t*)(smb + ASM_VT);
    __half*   Qs     = (__half*)smb;   // staging overlay (Ks region, 256x72h)

    const int tid  = threadIdx.x;
    const int lane = tid & 31;
    const int warp = tid >> 5;
    const int g    = lane >> 2;
    const int tk   = lane & 3;
    const int wq   = warp * 16;

    const uint32_t KsU = (uint32_t)__cvta_generic_to_shared(KsBase);
    const uint32_t VtU = (uint32_t)__cvta_generic_to_shared(VtBase);
    // ldmatrix per-lane row offsets: matrices {0,1}=rows 0-7, {2,3}=rows 8-15;
    // {0,2}=k-lo 16B, {1,3}=k-hi.
    const int rowbase = (lane & 7) + ((lane >> 4) << 3);
    const uint32_t kHalf = ((lane >> 3) & 1) << 4;
    const uint32_t laneK = rowbase * 144 + kHalf;
    const uint32_t laneV = rowbase * 272 + kHalf;

    const int qt = blockIdx.x, h = blockIdx.y, b = blockIdx.z;
    const __half* Qg = g_QKV + ((size_t)b * SEQ + qt * AQT) * STR3 + h * HDIM;
    const __half* Kg = g_QKV + (size_t)b * SEQ * STR3 + HID + h * HDIM;
    const __half* Vg = g_QKV + (size_t)b * SEQ * STR3 + 2 * HID + h * HDIM;

    // ---- stage Q (256x64 halfs) and extract fragments ----
#pragma unroll
    for (int i = 0; i < 4; ++i) {
        int s = tid + 512 * i, r = s >> 3, c8 = s & 7;
        *(uint4*)&Qs[r * KSR + c8 * 8] = *(const uint4*)&Qg[(size_t)r * STR3 + c8 * 8];
    }
    __syncthreads();

    uint32_t qa[4][4];
#pragma unroll
    for (int ks = 0; ks < 4; ++ks) {
        int r0 = wq + g, base = ks * 16 + 2 * tk;
        qa[ks][0] = *(const uint32_t*)&Qs[r0 * KSR + base];
        qa[ks][1] = *(const uint32_t*)&Qs[(r0 + 8) * KSR + base];
        qa[ks][2] = *(const uint32_t*)&Qs[r0 * KSR + base + 8];
        qa[ks][3] = *(const uint32_t*)&Qs[(r0 + 8) * KSR + base + 8];
    }
    __syncthreads();   // staging region free before KV prologue

    float oacc[8][4];
#pragma unroll
    for (int nf = 0; nf < 8; ++nf)
#pragma unroll
        for (int i = 0; i < 4; ++i) oacc[nf][i] = 0.f;
    float dp0 = 0.f, dp1 = 0.f;

    // V transpose mapping: thread covers keys (2*key2g, 2*key2g+1), dims vm*8..+7
    const int key2g = tid & 63;        // 0..63
    const int vm    = tid >> 6;        // 0..7
    uint4 va, vb4;

    // ---- prologue: V(0) transposed + K(0) cp.async (128 keys) ----
    {
        const __half* Vr = Vg + (size_t)(2 * key2g) * STR3 + vm * 8;
        va  = *(const uint4*)Vr;
        vb4 = *(const uint4*)(Vr + STR3);
        store_vt8(VtBase, va, vb4, vm, key2g);
#pragma unroll
        for (int i = 0; i < 2; ++i) {
            int s = tid + 512 * i, r = s >> 3, c8 = s & 7;   // 128 rows x 8 chunks
            cp16(&KsBase[r * KSR + c8 * 8], &Kg[(size_t)r * STR3 + c8 * 8]);
        }
        asm volatile("cp.async.commit_group;\n");
    }

    for (int kt = 0; kt < KT2; ++kt) {
        asm volatile("cp.async.wait_group 0;\n" ::: "memory");
        __syncthreads();   // K(kt) ready, Vt[kt&1] complete

        const bool nxt = (kt + 1 < KT2);
        if (nxt) {
            const __half* Vr = Vg + (size_t)((kt + 1) * 128 + 2 * key2g) * STR3 + vm * 8;
            va  = *(const uint4*)Vr;
            vb4 = *(const uint4*)(Vr + STR3);
            const __half* Kn = Kg + (size_t)(kt + 1) * 128 * STR3;
#pragma unroll
            for (int i = 0; i < 2; ++i) {
                int s = tid + 512 * i, r = s >> 3, c8 = s & 7;
                cp16(&KsBase[((kt + 1) & 1) * (KSBYTES / 2) + r * KSR + c8 * 8],
                     &Kn[(size_t)r * STR3 + c8 * 8]);
            }
            asm volatile("cp.async.commit_group;\n");
        }

        const uint32_t kBuf = KsU + (kt & 1) * KSBYTES + laneK;
        const uint32_t vBuf = VtU + (kt & 1) * VTBYTES + laneV;

#pragma unroll
        for (int sub = 0; sub < 2; ++sub) {
            const uint32_t kSub = kBuf + sub * 9216;   // +64 key rows
            const uint32_t vSub = vBuf + sub * 128;    // +64 keys (32 key2 words)

            // ---- S = Q K^T : 16q x 64k via ldmatrix.x4 (16 LDSM, 32 mmas) ----
            float sacc[8][4];
#pragma unroll
            for (int nf = 0; nf < 8; ++nf)
#pragma unroll
                for (int i = 0; i < 4; ++i) sacc[nf][i] = 0.f;
#pragma unroll
            for (int pair = 0; pair < 4; ++pair) {
#pragma unroll
                for (int ks = 0; ks < 4; ++ks) {
                    uint32_t b0, b1, b2, b3;
                    ldsm_x4(b0, b1, b2, b3, kSub + pair * 2304 + ks * 32);
                    uint32_t bvA[2] = {b0, b1}, bvB[2] = {b2, b3};
                    mma_f16(sacc[2 * pair],     qa[ks], bvA);
                    mma_f16(sacc[2 * pair + 1], qa[ks], bvB);
                }
            }

            // stash V(kt+1) transposed (once per kt, overlapped with compute)
            if (sub == 0 && nxt)
                store_vt8(VtBase + ((kt + 1) & 1) * (VTBYTES / 4), va, vb4, vm, key2g);

            // ---- P = sigmoid(scale*S) in registers -> A-frags ----
            uint32_t pfrag[4][4];
#pragma unroll
            for (int ks = 0; ks < 4; ++ks) {
#pragma unroll
                for (int half8 = 0; half8 < 2; ++half8) {
                    const float* s4 = sacc[2 * ks + half8];
                    float p00 = __fdividef(1.f, 1.f + __expf(-SCALE * s4[0]));
                    float p01 = __fdividef(1.f, 1.f + __expf(-SCALE * s4[1]));
                    float p10 = __fdividef(1.f, 1.f + __expf(-SCALE * s4[2]));
                    float p11 = __fdividef(1.f, 1.f + __expf(-SCALE * s4[3]));
                    dp0 += p00 + p01;
                    dp1 += p10 + p11;
                    pfrag[ks][half8 * 2 + 0] = h2u(__floats2half2_rn(p00, p01));
                    pfrag[ks][half8 * 2 + 1] = h2u(__floats2half2_rn(p10, p11));
                }
            }

            // ---- O += P V : 16q x 64d via ldmatrix.x4 (16 LDSM, 32 mmas) ----
#pragma unroll
            for (int pair = 0; pair < 4; ++pair) {
#pragma unroll
                for (int ks = 0; ks < 4; ++ks) {
                    uint32_t b0, b1, b2, b3;
                    ldsm_x4(b0, b1, b2, b3, vSub + pair * 4352 + ks * 32);
                    uint32_t bvA[2] = {b0, b1}, bvB[2] = {b2, b3};
                    mma_f16(oacc[2 * pair],     pfrag[ks], bvA);
                    mma_f16(oacc[2 * pair + 1], pfrag[ks], bvB);
                }
            }
        }
    }

    // ---- denominators: quad shfl reduction ----
    float d0 = dp0;
    d0 += __shfl_xor_sync(0xFFFFFFFFu, d0, 1);
    d0 += __shfl_xor_sync(0xFFFFFFFFu, d0, 2);
    float d1 = dp1;
    d1 += __shfl_xor_sync(0xFFFFFFFFu, d1, 1);
    d1 += __shfl_xor_sync(0xFFFFFFFFu, d1, 2);
    float inv0 = __fdividef(1.f, d0 + EPS);
    float inv1 = __fdividef(1.f, d1 + EPS);

    // ---- epilogue: fp16 attention output for the Wo GEMM ----
    __half* Ag = g_A + ((size_t)b * SEQ + qt * AQT) * HID + h * HDIM;
    int row0 = wq + g, row1 = wq + g + 8;
#pragma unroll
    for (int nf = 0; nf < 8; ++nf) {
        int c0 = nf * 8 + 2 * tk;
        *(uint32_t*)&Ag[(size_t)row0 * HID + c0] =
            h2u(__floats2half2_rn(oacc[nf][0] * inv0, oacc[nf][1] * inv0));
        *(uint32_t*)&Ag[(size_t)row1 * HID + c0] =
            h2u(__floats2half2_rn(oacc[nf][2] * inv1, oacc[nf][3] * inv1));
    }
}

// ---------------------------------------------------------------------------
extern "C" void kernel_launch(void* const* d_in, const int* in_sizes, int n_in,
                              void* d_out, int out_size)
{
    __half *QKVp, *Ap, *Xp, *Wp;
    cudaGetSymbolAddress((void**)&QKVp, g_QKV);
    cudaGetSymbolAddress((void**)&Ap, g_A);
    cudaGetSymbolAddress((void**)&Xp, g_X);
    cudaGetSymbolAddress((void**)&Wp, g_W);

    cudaFuncSetAttribute(attn_f16, cudaFuncAttributeMaxDynamicSharedMemorySize, ASM_TOTAL);

    const float* x  = (const float*)d_in[0];
    const float* Wq = (const float*)d_in[1];
    const float* Wk = (const float*)d_in[2];
    const float* Wv = (const float*)d_in[3];
    const float* Wo = (const float*)d_in[4];
    float* out = (float*)d_out;

    // fp32 -> fp16 conversions (2 launches)
    to_half_k<<<512, 256>>>((const float4*)x, (uint2*)Xp, MTOT * HID / 4);
    to_half_w4<<<512, 256>>>((const float4*)Wq, (const float4*)Wk,
                             (const float4*)Wv, (const float4*)Wo, (uint2*)Wp);

    // fused QKV projection: C[4096, 3072] = X @ [Wq;Wk;Wv]^T
    dim3 qkvGrid(STR3 / 128, MTOT / 128);  // (24, 32)
    gemm_f16<true><<<qkvGrid, 256>>>(Xp, Wp, QKVp, MTOT, STR3, HID);

    dim3 attnGrid(SEQ / AQT, NHEAD, Bsz);  // (8, 16, 2)
    attn_f16<<<attnGrid, 512, ASM_TOTAL>>>();

    dim3 oGrid(HID / 128, MTOT / 128);     // (8, 32)
    gemm_f16<false><<<oGrid, 256>>>(Ap, Wp + 3 * HID * HID, out, MTOT, HID, HID);
}

// round 16
// speedup vs baseline: 7.5232x; 1.0966x over previous
#include <cuda_runtime.h>
#include <cuda_fp16.h>
#include <stdint.h>
#include <math.h>

#define Bsz 2
#define SEQ 2048
#define HID 1024
#define NHEAD 16
#define HDIM 64
#define SCALE 0.125f
#define EPS 1e-6f
#define MTOT (Bsz*SEQ)   // 4096
#define STR3 (3*HID)     // fused QKV row stride

// Scratch (device globals: allocation-free)
__device__ __half g_QKV[MTOT * STR3];    // fused Q|K|V projections
__device__ __half g_A[MTOT * HID];
__device__ __half g_X[MTOT * HID];       // fp16 x
__device__ __half g_W[4 * HID * HID];    // fp16 Wq,Wk,Wv,Wo (contiguous)

// ---------------------------------------------------------------------------
// Helpers
// ---------------------------------------------------------------------------
__device__ __forceinline__ void mma_f16(float* d, const uint32_t* a, const uint32_t* b) {
    asm volatile(
        "mma.sync.aligned.m16n8k16.row.col.f32.f16.f16.f32 "
        "{%0,%1,%2,%3},{%4,%5,%6,%7},{%8,%9},{%0,%1,%2,%3};\n"
        : "+f"(d[0]), "+f"(d[1]), "+f"(d[2]), "+f"(d[3])
        : "r"(a[0]), "r"(a[1]), "r"(a[2]), "r"(a[3]), "r"(b[0]), "r"(b[1]));
}

__device__ __forceinline__ void ldsm_x4(uint32_t& r0, uint32_t& r1, uint32_t& r2,
                                        uint32_t& r3, uint32_t addr) {
    asm volatile("ldmatrix.sync.aligned.m8n8.x4.shared.b16 {%0,%1,%2,%3}, [%4];"
                 : "=r"(r0), "=r"(r1), "=r"(r2), "=r"(r3) : "r"(addr));
}

__device__ __forceinline__ void cp16(void* smem_dst, const void* gmem_src) {
    uint32_t s = (uint32_t)__cvta_generic_to_shared(smem_dst);
    asm volatile("cp.async.cg.shared.global [%0], [%1], 16;\n" :: "r"(s), "l"(gmem_src));
}

__device__ __forceinline__ uint32_t h2u(__half2 h) { return *reinterpret_cast<uint32_t*>(&h); }

// ---------------------------------------------------------------------------
// Fused f32 -> f16 conversion: x (1<<20 float4s) then 4 weights (1<<18 each)
// ---------------------------------------------------------------------------
__global__ void to_half_all(const float4* __restrict__ x,
                            const float4* __restrict__ w0, const float4* __restrict__ w1,
                            const float4* __restrict__ w2, const float4* __restrict__ w3,
                            uint2* __restrict__ xout, uint2* __restrict__ wout)
{
    const int nx = MTOT * HID / 4;        // 1<<20
    const int nw = HID * HID / 4;         // 1<<18
    const int total = nx + 4 * nw;
    for (int i = blockIdx.x * blockDim.x + threadIdx.x; i < total; i += gridDim.x * blockDim.x) {
        float4 v;
        uint2* dst;
        if (i < nx) {
            v = x[i]; dst = xout + i;
        } else {
            int j = i - nx, seg = j >> 18, off = j & (nw - 1);
            const float4* src = (seg == 0) ? w0 : (seg == 1) ? w1 : (seg == 2) ? w2 : w3;
            v = src[off]; dst = wout + j;
        }
        *dst = make_uint2(h2u(__floats2half2_rn(v.x, v.y)),
                          h2u(__floats2half2_rn(v.z, v.w)));
    }
}

// ---------------------------------------------------------------------------
// FP16 GEMM v2: C[M,N] = A[M,K] * B[N,K]^T.  ldmatrix fragments + cp.async
// double-buffered K-tiles (BK=64 halfs), ONE barrier per tile.
// CTA tile 128x128, 8 warps, warp tile 32x64. Dynamic smem 72 KB, 2 CTA/SM.
// Same mma order as R15 -> bit-identical results.
// ---------------------------------------------------------------------------
#define GSB 144                    // smem row stride bytes (72 halfs)
#define GTB (128 * GSB)            // 18432 B per 128-row buffer
#define G_SMEM (4 * GTB)           // As[2] | Bs[2] = 73728 B

template<bool HOUT>
__global__ __launch_bounds__(256, 2) void gemm_f16(
    const __half* __restrict__ A, const __half* __restrict__ B,
    void* __restrict__ Cv, int M, int N, int K)
{
    extern __shared__ __half smg[];
    __half* AsBase = smg;                       // 2 x 128 x 72h
    __half* BsBase = smg + 2 * 128 * 72;

    const int tid  = threadIdx.x;
    const int lane = tid & 31;
    const int warp = tid >> 5;
    const int g    = lane >> 2;
    const int tk   = lane & 3;
    const int wm   = (warp & 3) * 32;
    const int wn   = (warp >> 2) * 64;
    const int mBase = blockIdx.y * 128;
    const int nBase = blockIdx.x * 128;

    const uint32_t AsU = (uint32_t)__cvta_generic_to_shared(AsBase);
    const uint32_t BsU = (uint32_t)__cvta_generic_to_shared(BsBase);
    // A-frag lane map: m0=rows0-7 kLo, m1=rows8-15 kLo, m2=rows0-7 kHi, m3=rows8-15 kHi
    const int rowA = (lane & 7) + ((lane >> 3) & 1) * 8;
    const uint32_t colA = (lane >> 4) << 4;
    // B-frag lane map: m0=rows0-7 kLo, m1=rows0-7 kHi, m2=rows8-15 kLo, m3=rows8-15 kHi
    const int rowB = (lane & 7) + ((lane >> 4) << 3);
    const uint32_t colB = ((lane >> 3) & 1) << 4;

    float acc[2][8][4];
#pragma unroll
    for (int mf = 0; mf < 2; ++mf)
#pragma unroll
        for (int nf = 0; nf < 8; ++nf)
#pragma unroll
            for (int i = 0; i < 4; ++i) acc[mf][nf][i] = 0.f;

    const int T = K / 64;   // 16

    // prologue: tile 0 -> buf 0 (128 rows x 8 x 16B chunks per matrix)
#pragma unroll
    for (int i = 0; i < 4; ++i) {
        int s = tid + 256 * i, r = s >> 3, c8 = s & 7;
        cp16((char*)AsBase + r * GSB + c8 * 16, &A[(size_t)(mBase + r) * K + c8 * 8]);
        cp16((char*)BsBase + r * GSB + c8 * 16, &B[(size_t)(nBase + r) * K + c8 * 8]);
    }
    asm volatile("cp.async.commit_group;\n");

    for (int t = 0; t < T; ++t) {
        asm volatile("cp.async.wait_group 0;\n" ::: "memory");
        __syncthreads();

        if (t + 1 < T) {
            int kOff = (t + 1) * 64;
            char* Ad = (char*)AsBase + ((t + 1) & 1) * GTB;
            char* Bd = (char*)BsBase + ((t + 1) & 1) * GTB;
#pragma unroll
            for (int i = 0; i < 4; ++i) {
                int s = tid + 256 * i, r = s >> 3, c8 = s & 7;
                cp16(Ad + r * GSB + c8 * 16, &A[(size_t)(mBase + r) * K + kOff + c8 * 8]);
                cp16(Bd + r * GSB + c8 * 16, &B[(size_t)(nBase + r) * K + kOff + c8 * 8]);
            }
            asm volatile("cp.async.commit_group;\n");
        }

        const uint32_t aT = AsU + (t & 1) * GTB;
        const uint32_t bT = BsU + (t & 1) * GTB;
#pragma unroll
        for (int ks = 0; ks < 4; ++ks) {
            const uint32_t k0b = ks * 32;
            uint32_t av[2][4];
#pragma unroll
            for (int mf = 0; mf < 2; ++mf)
                ldsm_x4(av[mf][0], av[mf][1], av[mf][2], av[mf][3],
                        aT + (wm + mf * 16 + rowA) * GSB + k0b + colA);
            uint32_t bv[8][2];
#pragma unroll
            for (int nfp = 0; nfp < 4; ++nfp) {
                uint32_t m0, m1, m2, m3;
                ldsm_x4(m0, m1, m2, m3,
                        bT + (wn + nfp * 16 + rowB) * GSB + k0b + colB);
                bv[2 * nfp][0] = m0;     bv[2 * nfp][1] = m1;
                bv[2 * nfp + 1][0] = m2; bv[2 * nfp + 1][1] = m3;
            }
#pragma unroll
            for (int mf = 0; mf < 2; ++mf)
#pragma unroll
                for (int nf = 0; nf < 8; ++nf)
                    mma_f16(acc[mf][nf], av[mf], bv[nf]);
        }
    }

#pragma unroll
    for (int mf = 0; mf < 2; ++mf) {
        int r0 = mBase + wm + mf * 16 + g;
#pragma unroll
        for (int nf = 0; nf < 8; ++nf) {
            int c0 = nBase + wn + nf * 8 + 2 * tk;
            if (HOUT) {
                __half* C = (__half*)Cv;
                *(uint32_t*)&C[(size_t)r0 * N + c0] =
                    h2u(__floats2half2_rn(acc[mf][nf][0], acc[mf][nf][1]));
                *(uint32_t*)&C[(size_t)(r0 + 8) * N + c0] =
                    h2u(__floats2half2_rn(acc[mf][nf][2], acc[mf][nf][3]));
            } else {
                float* C = (float*)Cv;
                *(float2*)&C[(size_t)r0 * N + c0] = make_float2(acc[mf][nf][0], acc[mf][nf][1]);
                *(float2*)&C[(size_t)(r0 + 8) * N + c0] = make_float2(acc[mf][nf][2], acc[mf][nf][3]);
            }
        }
    }
}

// ---------------------------------------------------------------------------
// FP16 sigmoid attention v6 (unchanged from R15 passing kernel)
// ---------------------------------------------------------------------------
#define AQT 256
#define KT2 16                    // SEQ / 128
#define KSR 72                    // Ks row stride (halfs) = 144 B
#define KSBYTES (128 * 144)       // 18432 B per K buffer
#define VTS 68                    // Vt row stride (uint32) = 272 B
#define VTBYTES (64 * 272)        // 17408 B per V buffer
#define ASM_VT (2 * KSBYTES)      // 36864
#define ASM_TOTAL (ASM_VT + 2 * VTBYTES)   // 71680 B

__device__ __forceinline__ void store_vt8(uint32_t* Vt, uint4 A, uint4 B, int vm, int key2)
{
    const __half2* a = (const __half2*)&A;
    const __half2* bb = (const __half2*)&B;
#pragma unroll
    for (int j = 0; j < 4; ++j) {
        __half2 aj = a[j], bj = bb[j];
        Vt[(vm * 8 + 2 * j)     * VTS + key2] = h2u(__halves2half2(aj.x, bj.x));
        Vt[(vm * 8 + 2 * j + 1) * VTS + key2] = h2u(__halves2half2(aj.y, bj.y));
    }
}

__global__ __launch_bounds__(512, 1) void attn_f16()
{
    extern __shared__ char smb[];
    __half*   KsBase = (__half*)smb;
    uint32_t* VtBase = (uint32_t*)(smb + ASM_VT);
    __half*   Qs     = (__half*)smb;   // staging overlay

    const int tid  = threadIdx.x;
    const int lane = tid & 31;
    const int warp = tid >> 5;
    const int g    = lane >> 2;
    const int tk   = lane & 3;
    const int wq   = warp * 16;

    const uint32_t KsU = (uint32_t)__cvta_generic_to_shared(KsBase);
    const uint32_t VtU = (uint32_t)__cvta_generic_to_shared(VtBase);
    const int rowbase = (lane & 7) + ((lane >> 4) << 3);
    const uint32_t kHalf = ((lane >> 3) & 1) << 4;
    const uint32_t laneK = rowbase * 144 + kHalf;
    const uint32_t laneV = rowbase * 272 + kHalf;

    const int qt = blockIdx.x, h = blockIdx.y, b = blockIdx.z;
    const __half* Qg = g_QKV + ((size_t)b * SEQ + qt * AQT) * STR3 + h * HDIM;
    const __half* Kg = g_QKV + (size_t)b * SEQ * STR3 + HID + h * HDIM;
    const __half* Vg = g_QKV + (size_t)b * SEQ * STR3 + 2 * HID + h * HDIM;

    // ---- stage Q and extract fragments ----
#pragma unroll
    for (int i = 0; i < 4; ++i) {
        int s = tid + 512 * i, r = s >> 3, c8 = s & 7;
        *(uint4*)&Qs[r * KSR + c8 * 8] = *(const uint4*)&Qg[(size_t)r * STR3 + c8 * 8];
    }
    __syncthreads();

    uint32_t qa[4][4];
#pragma unroll
    for (int ks = 0; ks < 4; ++ks) {
        int r0 = wq + g, base = ks * 16 + 2 * tk;
        qa[ks][0] = *(const uint32_t*)&Qs[r0 * KSR + base];
        qa[ks][1] = *(const uint32_t*)&Qs[(r0 + 8) * KSR + base];
        qa[ks][2] = *(const uint32_t*)&Qs[r0 * KSR + base + 8];
        qa[ks][3] = *(const uint32_t*)&Qs[(r0 + 8) * KSR + base + 8];
    }
    __syncthreads();

    float oacc[8][4];
#pragma unroll
    for (int nf = 0; nf < 8; ++nf)
#pragma unroll
        for (int i = 0; i < 4; ++i) oacc[nf][i] = 0.f;
    float dp0 = 0.f, dp1 = 0.f;

    const int key2g = tid & 63;
    const int vm    = tid >> 6;
    uint4 va, vb4;

    {
        const __half* Vr = Vg + (size_t)(2 * key2g) * STR3 + vm * 8;
        va  = *(const uint4*)Vr;
        vb4 = *(const uint4*)(Vr + STR3);
        store_vt8(VtBase, va, vb4, vm, key2g);
#pragma unroll
        for (int i = 0; i < 2; ++i) {
            int s = tid + 512 * i, r = s >> 3, c8 = s & 7;
            cp16(&KsBase[r * KSR + c8 * 8], &Kg[(size_t)r * STR3 + c8 * 8]);
        }
        asm volatile("cp.async.commit_group;\n");
    }

    for (int kt = 0; kt < KT2; ++kt) {
        asm volatile("cp.async.wait_group 0;\n" ::: "memory");
        __syncthreads();

        const bool nxt = (kt + 1 < KT2);
        if (nxt) {
            const __half* Vr = Vg + (size_t)((kt + 1) * 128 + 2 * key2g) * STR3 + vm * 8;
            va  = *(const uint4*)Vr;
            vb4 = *(const uint4*)(Vr + STR3);
            const __half* Kn = Kg + (size_t)(kt + 1) * 128 * STR3;
#pragma unroll
            for (int i = 0; i < 2; ++i) {
                int s = tid + 512 * i, r = s >> 3, c8 = s & 7;
                cp16(&KsBase[((kt + 1) & 1) * (KSBYTES / 2) + r * KSR + c8 * 8],
                     &Kn[(size_t)r * STR3 + c8 * 8]);
            }
            asm volatile("cp.async.commit_group;\n");
        }

        const uint32_t kBuf = KsU + (kt & 1) * KSBYTES + laneK;
        const uint32_t vBuf = VtU + (kt & 1) * VTBYTES + laneV;

#pragma unroll
        for (int sub = 0; sub < 2; ++sub) {
            const uint32_t kSub = kBuf + sub * 9216;
            const uint32_t vSub = vBuf + sub * 128;

            float sacc[8][4];
#pragma unroll
            for (int nf = 0; nf < 8; ++nf)
#pragma unroll
                for (int i = 0; i < 4; ++i) sacc[nf][i] = 0.f;
#pragma unroll
            for (int pair = 0; pair < 4; ++pair) {
#pragma unroll
                for (int ks = 0; ks < 4; ++ks) {
                    uint32_t b0, b1, b2, b3;
                    ldsm_x4(b0, b1, b2, b3, kSub + pair * 2304 + ks * 32);
                    uint32_t bvA[2] = {b0, b1}, bvB[2] = {b2, b3};
                    mma_f16(sacc[2 * pair],     qa[ks], bvA);
                    mma_f16(sacc[2 * pair + 1], qa[ks], bvB);
                }
            }

            if (sub == 0 && nxt)
                store_vt8(VtBase + ((kt + 1) & 1) * (VTBYTES / 4), va, vb4, vm, key2g);

            uint32_t pfrag[4][4];
#pragma unroll
            for (int ks = 0; ks < 4; ++ks) {
#pragma unroll
                for (int half8 = 0; half8 < 2; ++half8) {
                    const float* s4 = sacc[2 * ks + half8];
                    float p00 = __fdividef(1.f, 1.f + __expf(-SCALE * s4[0]));
                    float p01 = __fdividef(1.f, 1.f + __expf(-SCALE * s4[1]));
                    float p10 = __fdividef(1.f, 1.f + __expf(-SCALE * s4[2]));
                    float p11 = __fdividef(1.f, 1.f + __expf(-SCALE * s4[3]));
                    dp0 += p00 + p01;
                    dp1 += p10 + p11;
                    pfrag[ks][half8 * 2 + 0] = h2u(__floats2half2_rn(p00, p01));
                    pfrag[ks][half8 * 2 + 1] = h2u(__floats2half2_rn(p10, p11));
                }
            }

#pragma unroll
            for (int pair = 0; pair < 4; ++pair) {
#pragma unroll
                for (int ks = 0; ks < 4; ++ks) {
                    uint32_t b0, b1, b2, b3;
                    ldsm_x4(b0, b1, b2, b3, vSub + pair * 4352 + ks * 32);
                    uint32_t bvA[2] = {b0, b1}, bvB[2] = {b2, b3};
                    mma_f16(oacc[2 * pair],     pfrag[ks], bvA);
                    mma_f16(oacc[2 * pair + 1], pfrag[ks], bvB);
                }
            }
        }
    }

    float d0 = dp0;
    d0 += __shfl_xor_sync(0xFFFFFFFFu, d0, 1);
    d0 += __shfl_xor_sync(0xFFFFFFFFu, d0, 2);
    float d1 = dp1;
    d1 += __shfl_xor_sync(0xFFFFFFFFu, d1, 1);
    d1 += __shfl_xor_sync(0xFFFFFFFFu, d1, 2);
    float inv0 = __fdividef(1.f, d0 + EPS);
    float inv1 = __fdividef(1.f, d1 + EPS);

    __half* Ag = g_A + ((size_t)b * SEQ + qt * AQT) * HID + h * HDIM;
    int row0 = wq + g, row1 = wq + g + 8;
#pragma unroll
    for (int nf = 0; nf < 8; ++nf) {
        int c0 = nf * 8 + 2 * tk;
        *(uint32_t*)&Ag[(size_t)row0 * HID + c0] =
            h2u(__floats2half2_rn(oacc[nf][0] * inv0, oacc[nf][1] * inv0));
        *(uint32_t*)&Ag[(size_t)row1 * HID + c0] =
            h2u(__floats2half2_rn(oacc[nf][2] * inv1, oacc[nf][3] * inv1));
    }
}

// ---------------------------------------------------------------------------
extern "C" void kernel_launch(void* const* d_in, const int* in_sizes, int n_in,
                              void* d_out, int out_size)
{
    __half *QKVp, *Ap, *Xp, *Wp;
    cudaGetSymbolAddress((void**)&QKVp, g_QKV);
    cudaGetSymbolAddress((void**)&Ap, g_A);
    cudaGetSymbolAddress((void**)&Xp, g_X);
    cudaGetSymbolAddress((void**)&Wp, g_W);

    cudaFuncSetAttribute(attn_f16, cudaFuncAttributeMaxDynamicSharedMemorySize, ASM_TOTAL);
    cudaFuncSetAttribute(gemm_f16<true>,  cudaFuncAttributeMaxDynamicSharedMemorySize, G_SMEM);
    cudaFuncSetAttribute(gemm_f16<false>, cudaFuncAttributeMaxDynamicSharedMemorySize, G_SMEM);

    const float* x  = (const float*)d_in[0];
    const float* Wq = (const float*)d_in[1];
    const float* Wk = (const float*)d_in[2];
    const float* Wv = (const float*)d_in[3];
    const float* Wo = (const float*)d_in[4];
    float* out = (float*)d_out;

    // fp32 -> fp16 conversion (single launch)
    to_half_all<<<512, 256>>>((const float4*)x,
                              (const float4*)Wq, (const float4*)Wk,
                              (const float4*)Wv, (const float4*)Wo,
                              (uint2*)Xp, (uint2*)Wp);

    // fused QKV projection: C[4096, 3072] = X @ [Wq;Wk;Wv]^T
    dim3 qkvGrid(STR3 / 128, MTOT / 128);  // (24, 32)
    gemm_f16<true><<<qkvGrid, 256, G_SMEM>>>(Xp, Wp, QKVp, MTOT, STR3, HID);

    dim3 attnGrid(SEQ / AQT, NHEAD, Bsz);  // (8, 16, 2)
    attn_f16<<<attnGrid, 512, ASM_TOTAL>>>();

    dim3 oGrid(HID / 128, MTOT / 128);     // (8, 32)
    gemm_f16<false><<<oGrid, 256, G_SMEM>>>(Ap, Wp + 3 * HID * HID, out, MTOT, HID, HID);
}

// round 17
// speedup vs baseline: 8.1982x; 1.0897x over previous
#include <cuda_runtime.h>
#include <cuda_fp16.h>
#include <stdint.h>
#include <math.h>

#define Bsz 2
#define SEQ 2048
#define HID 1024
#define NHEAD 16
#define HDIM 64
#define SCALE 0.125f
#define HSCALE 0.0625f   // SCALE/2 for the tanh form of sigmoid
#define EPS 1e-6f
#define MTOT (Bsz*SEQ)   // 4096
#define STR3 (3*HID)     // fused QKV row stride

// Scratch (device globals: allocation-free)
__device__ __half g_QKV[MTOT * STR3];    // fused Q|K|V projections
__device__ __half g_A[MTOT * HID];
__device__ __half g_X[MTOT * HID];       // fp16 x
__device__ __half g_W[4 * HID * HID];    // fp16 Wq,Wk,Wv,Wo (contiguous)

// ---------------------------------------------------------------------------
// Helpers
// ---------------------------------------------------------------------------
__device__ __forceinline__ void mma_f16(float* d, const uint32_t* a, const uint32_t* b) {
    asm volatile(
        "mma.sync.aligned.m16n8k16.row.col.f32.f16.f16.f32 "
        "{%0,%1,%2,%3},{%4,%5,%6,%7},{%8,%9},{%0,%1,%2,%3};\n"
        : "+f"(d[0]), "+f"(d[1]), "+f"(d[2]), "+f"(d[3])
        : "r"(a[0]), "r"(a[1]), "r"(a[2]), "r"(a[3]), "r"(b[0]), "r"(b[1]));
}

__device__ __forceinline__ void ldsm_x4(uint32_t& r0, uint32_t& r1, uint32_t& r2,
                                        uint32_t& r3, uint32_t addr) {
    asm volatile("ldmatrix.sync.aligned.m8n8.x4.shared.b16 {%0,%1,%2,%3}, [%4];"
                 : "=r"(r0), "=r"(r1), "=r"(r2), "=r"(r3) : "r"(addr));
}

__device__ __forceinline__ void cp16(void* smem_dst, const void* gmem_src) {
    uint32_t s = (uint32_t)__cvta_generic_to_shared(smem_dst);
    asm volatile("cp.async.cg.shared.global [%0], [%1], 16;\n" :: "r"(s), "l"(gmem_src));
}

__device__ __forceinline__ uint32_t h2u(__half2 h) { return *reinterpret_cast<uint32_t*>(&h); }

__device__ __forceinline__ float tanha(float x) {
    float r;
    asm("tanh.approx.f32 %0, %1;" : "=f"(r) : "f"(x));
    return r;
}
// sigmoid(SCALE*s) = 0.5*tanh(HSCALE*s) + 0.5  (1 MUFU instead of 2)
__device__ __forceinline__ float sigmo(float s) {
    return fmaf(0.5f, tanha(HSCALE * s), 0.5f);
}

// ---------------------------------------------------------------------------
// Fused f32 -> f16 conversion: x (1<<20 float4s) then 4 weights (1<<18 each)
// ---------------------------------------------------------------------------
__global__ void to_half_all(const float4* __restrict__ x,
                            const float4* __restrict__ w0, const float4* __restrict__ w1,
                            const float4* __restrict__ w2, const float4* __restrict__ w3,
                            uint2* __restrict__ xout, uint2* __restrict__ wout)
{
    const int nx = MTOT * HID / 4;        // 1<<20
    const int nw = HID * HID / 4;         // 1<<18
    const int total = nx + 4 * nw;
    for (int i = blockIdx.x * blockDim.x + threadIdx.x; i < total; i += gridDim.x * blockDim.x) {
        float4 v;
        uint2* dst;
        if (i < nx) {
            v = x[i]; dst = xout + i;
        } else {
            int j = i - nx, seg = j >> 18, off = j & (nw - 1);
            const float4* src = (seg == 0) ? w0 : (seg == 1) ? w1 : (seg == 2) ? w2 : w3;
            v = src[off]; dst = wout + j;
        }
        *dst = make_uint2(h2u(__floats2half2_rn(v.x, v.y)),
                          h2u(__floats2half2_rn(v.z, v.w)));
    }
}

// ---------------------------------------------------------------------------
// FP16 GEMM v2 (unchanged from R16 passing kernel)
// ---------------------------------------------------------------------------
#define GSB 144
#define GTB (128 * GSB)
#define G_SMEM (4 * GTB)

template<bool HOUT>
__global__ __launch_bounds__(256, 2) void gemm_f16(
    const __half* __restrict__ A, const __half* __restrict__ B,
    void* __restrict__ Cv, int M, int N, int K)
{
    extern __shared__ __half smg[];
    __half* AsBase = smg;
    __half* BsBase = smg + 2 * 128 * 72;

    const int tid  = threadIdx.x;
    const int lane = tid & 31;
    const int warp = tid >> 5;
    const int g    = lane >> 2;
    const int tk   = lane & 3;
    const int wm   = (warp & 3) * 32;
    const int wn   = (warp >> 2) * 64;
    const int mBase = blockIdx.y * 128;
    const int nBase = blockIdx.x * 128;

    const uint32_t AsU = (uint32_t)__cvta_generic_to_shared(AsBase);
    const uint32_t BsU = (uint32_t)__cvta_generic_to_shared(BsBase);
    const int rowA = (lane & 7) + ((lane >> 3) & 1) * 8;
    const uint32_t colA = (lane >> 4) << 4;
    const int rowB = (lane & 7) + ((lane >> 4) << 3);
    const uint32_t colB = ((lane >> 3) & 1) << 4;

    float acc[2][8][4];
#pragma unroll
    for (int mf = 0; mf < 2; ++mf)
#pragma unroll
        for (int nf = 0; nf < 8; ++nf)
#pragma unroll
            for (int i = 0; i < 4; ++i) acc[mf][nf][i] = 0.f;

    const int T = K / 64;

#pragma unroll
    for (int i = 0; i < 4; ++i) {
        int s = tid + 256 * i, r = s >> 3, c8 = s & 7;
        cp16((char*)AsBase + r * GSB + c8 * 16, &A[(size_t)(mBase + r) * K + c8 * 8]);
        cp16((char*)BsBase + r * GSB + c8 * 16, &B[(size_t)(nBase + r) * K + c8 * 8]);
    }
    asm volatile("cp.async.commit_group;\n");

    for (int t = 0; t < T; ++t) {
        asm volatile("cp.async.wait_group 0;\n" ::: "memory");
        __syncthreads();

        if (t + 1 < T) {
            int kOff = (t + 1) * 64;
            char* Ad = (char*)AsBase + ((t + 1) & 1) * GTB;
            char* Bd = (char*)BsBase + ((t + 1) & 1) * GTB;
#pragma unroll
            for (int i = 0; i < 4; ++i) {
                int s = tid + 256 * i, r = s >> 3, c8 = s & 7;
                cp16(Ad + r * GSB + c8 * 16, &A[(size_t)(mBase + r) * K + kOff + c8 * 8]);
                cp16(Bd + r * GSB + c8 * 16, &B[(size_t)(nBase + r) * K + kOff + c8 * 8]);
            }
            asm volatile("cp.async.commit_group;\n");
        }

        const uint32_t aT = AsU + (t & 1) * GTB;
        const uint32_t bT = BsU + (t & 1) * GTB;
#pragma unroll
        for (int ks = 0; ks < 4; ++ks) {
            const uint32_t k0b = ks * 32;
            uint32_t av[2][4];
#pragma unroll
            for (int mf = 0; mf < 2; ++mf)
                ldsm_x4(av[mf][0], av[mf][1], av[mf][2], av[mf][3],
                        aT + (wm + mf * 16 + rowA) * GSB + k0b + colA);
            uint32_t bv[8][2];
#pragma unroll
            for (int nfp = 0; nfp < 4; ++nfp) {
                uint32_t m0, m1, m2, m3;
                ldsm_x4(m0, m1, m2, m3,
                        bT + (wn + nfp * 16 + rowB) * GSB + k0b + colB);
                bv[2 * nfp][0] = m0;     bv[2 * nfp][1] = m1;
                bv[2 * nfp + 1][0] = m2; bv[2 * nfp + 1][1] = m3;
            }
#pragma unroll
            for (int mf = 0; mf < 2; ++mf)
#pragma unroll
                for (int nf = 0; nf < 8; ++nf)
                    mma_f16(acc[mf][nf], av[mf], bv[nf]);
        }
    }

#pragma unroll
    for (int mf = 0; mf < 2; ++mf) {
        int r0 = mBase + wm + mf * 16 + g;
#pragma unroll
        for (int nf = 0; nf < 8; ++nf) {
            int c0 = nBase + wn + nf * 8 + 2 * tk;
            if (HOUT) {
                __half* C = (__half*)Cv;
                *(uint32_t*)&C[(size_t)r0 * N + c0] =
                    h2u(__floats2half2_rn(acc[mf][nf][0], acc[mf][nf][1]));
                *(uint32_t*)&C[(size_t)(r0 + 8) * N + c0] =
                    h2u(__floats2half2_rn(acc[mf][nf][2], acc[mf][nf][3]));
            } else {
                float* C = (float*)Cv;
                *(float2*)&C[(size_t)r0 * N + c0] = make_float2(acc[mf][nf][0], acc[mf][nf][1]);
                *(float2*)&C[(size_t)(r0 + 8) * N + c0] = make_float2(acc[mf][nf][2], acc[mf][nf][3]);
            }
        }
    }
}

// ---------------------------------------------------------------------------
// FP16 sigmoid attention v7: v6 + tanh-form sigmoid (half the MUFU ops).
// ---------------------------------------------------------------------------
#define AQT 256
#define KT2 16
#define KSR 72
#define KSBYTES (128 * 144)
#define VTS 68
#define VTBYTES (64 * 272)
#define ASM_VT (2 * KSBYTES)
#define ASM_TOTAL (ASM_VT + 2 * VTBYTES)

__device__ __forceinline__ void store_vt8(uint32_t* Vt, uint4 A, uint4 B, int vm, int key2)
{
    const __half2* a = (const __half2*)&A;
    const __half2* bb = (const __half2*)&B;
#pragma unroll
    for (int j = 0; j < 4; ++j) {
        __half2 aj = a[j], bj = bb[j];
        Vt[(vm * 8 + 2 * j)     * VTS + key2] = h2u(__halves2half2(aj.x, bj.x));
        Vt[(vm * 8 + 2 * j + 1) * VTS + key2] = h2u(__halves2half2(aj.y, bj.y));
    }
}

__global__ __launch_bounds__(512, 1) void attn_f16()
{
    extern __shared__ char smb[];
    __half*   KsBase = (__half*)smb;
    uint32_t* VtBase = (uint32_t*)(smb + ASM_VT);
    __half*   Qs     = (__half*)smb;

    const int tid  = threadIdx.x;
    const int lane = tid & 31;
    const int warp = tid >> 5;
    const int g    = lane >> 2;
    const int tk   = lane & 3;
    const int wq   = warp * 16;

    const uint32_t KsU = (uint32_t)__cvta_generic_to_shared(KsBase);
    const uint32_t VtU = (uint32_t)__cvta_generic_to_shared(VtBase);
    const int rowbase = (lane & 7) + ((lane >> 4) << 3);
    const uint32_t kHalf = ((lane >> 3) & 1) << 4;
    const uint32_t laneK = rowbase * 144 + kHalf;
    const uint32_t laneV = rowbase * 272 + kHalf;

    const int qt = blockIdx.x, h = blockIdx.y, b = blockIdx.z;
    const __half* Qg = g_QKV + ((size_t)b * SEQ + qt * AQT) * STR3 + h * HDIM;
    const __half* Kg = g_QKV + (size_t)b * SEQ * STR3 + HID + h * HDIM;
    const __half* Vg = g_QKV + (size_t)b * SEQ * STR3 + 2 * HID + h * HDIM;

#pragma unroll
    for (int i = 0; i < 4; ++i) {
        int s = tid + 512 * i, r = s >> 3, c8 = s & 7;
        *(uint4*)&Qs[r * KSR + c8 * 8] = *(const uint4*)&Qg[(size_t)r * STR3 + c8 * 8];
    }
    __syncthreads();

    uint32_t qa[4][4];
#pragma unroll
    for (int ks = 0; ks < 4; ++ks) {
        int r0 = wq + g, base = ks * 16 + 2 * tk;
        qa[ks][0] = *(const uint32_t*)&Qs[r0 * KSR + base];
        qa[ks][1] = *(const uint32_t*)&Qs[(r0 + 8) * KSR + base];
        qa[ks][2] = *(const uint32_t*)&Qs[r0 * KSR + base + 8];
        qa[ks][3] = *(const uint32_t*)&Qs[(r0 + 8) * KSR + base + 8];
    }
    __syncthreads();

    float oacc[8][4];
#pragma unroll
    for (int nf = 0; nf < 8; ++nf)
#pragma unroll
        for (int i = 0; i < 4; ++i) oacc[nf][i] = 0.f;
    float dp0 = 0.f, dp1 = 0.f;

    const int key2g = tid & 63;
    const int vm    = tid >> 6;
    uint4 va, vb4;

    {
        const __half* Vr = Vg + (size_t)(2 * key2g) * STR3 + vm * 8;
        va  = *(const uint4*)Vr;
        vb4 = *(const uint4*)(Vr + STR3);
        store_vt8(VtBase, va, vb4, vm, key2g);
#pragma unroll
        for (int i = 0; i < 2; ++i) {
            int s = tid + 512 * i, r = s >> 3, c8 = s & 7;
            cp16(&KsBase[r * KSR + c8 * 8], &Kg[(size_t)r * STR3 + c8 * 8]);
        }
        asm volatile("cp.async.commit_group;\n");
    }

    for (int kt = 0; kt < KT2; ++kt) {
        asm volatile("cp.async.wait_group 0;\n" ::: "memory");
        __syncthreads();

        const bool nxt = (kt + 1 < KT2);
        if (nxt) {
            const __half* Vr = Vg + (size_t)((kt + 1) * 128 + 2 * key2g) * STR3 + vm * 8;
            va  = *(const uint4*)Vr;
            vb4 = *(const uint4*)(Vr + STR3);
            const __half* Kn = Kg + (size_t)(kt + 1) * 128 * STR3;
#pragma unroll
            for (int i = 0; i < 2; ++i) {
                int s = tid + 512 * i, r = s >> 3, c8 = s & 7;
                cp16(&KsBase[((kt + 1) & 1) * (KSBYTES / 2) + r * KSR + c8 * 8],
                     &Kn[(size_t)r * STR3 + c8 * 8]);
            }
            asm volatile("cp.async.commit_group;\n");
        }

        const uint32_t kBuf = KsU + (kt & 1) * KSBYTES + laneK;
        const uint32_t vBuf = VtU + (kt & 1) * VTBYTES + laneV;

#pragma unroll
        for (int sub = 0; sub < 2; ++sub) {
            const uint32_t kSub = kBuf + sub * 9216;
            const uint32_t vSub = vBuf + sub * 128;

            float sacc[8][4];
#pragma unroll
            for (int nf = 0; nf < 8; ++nf)
#pragma unroll
                for (int i = 0; i < 4; ++i) sacc[nf][i] = 0.f;
#pragma unroll
            for (int pair = 0; pair < 4; ++pair) {
#pragma unroll
                for (int ks = 0; ks < 4; ++ks) {
                    uint32_t b0, b1, b2, b3;
                    ldsm_x4(b0, b1, b2, b3, kSub + pair * 2304 + ks * 32);
                    uint32_t bvA[2] = {b0, b1}, bvB[2] = {b2, b3};
                    mma_f16(sacc[2 * pair],     qa[ks], bvA);
                    mma_f16(sacc[2 * pair + 1], qa[ks], bvB);
                }
            }

            if (sub == 0 && nxt)
                store_vt8(VtBase + ((kt + 1) & 1) * (VTBYTES / 4), va, vb4, vm, key2g);

            // ---- P = sigmoid via tanh (1 MUFU/value) -> A-frags ----
            uint32_t pfrag[4][4];
#pragma unroll
            for (int ks = 0; ks < 4; ++ks) {
#pragma unroll
                for (int half8 = 0; half8 < 2; ++half8) {
                    const float* s4 = sacc[2 * ks + half8];
                    float p00 = sigmo(s4[0]);
                    float p01 = sigmo(s4[1]);
                    float p10 = sigmo(s4[2]);
                    float p11 = sigmo(s4[3]);
                    dp0 += p00 + p01;
                    dp1 += p10 + p11;
                    pfrag[ks][half8 * 2 + 0] = h2u(__floats2half2_rn(p00, p01));
                    pfrag[ks][half8 * 2 + 1] = h2u(__floats2half2_rn(p10, p11));
                }
            }

#pragma unroll
            for (int pair = 0; pair < 4; ++pair) {
#pragma unroll
                for (int ks = 0; ks < 4; ++ks) {
                    uint32_t b0, b1, b2, b3;
                    ldsm_x4(b0, b1, b2, b3, vSub + pair * 4352 + ks * 32);
                    uint32_t bvA[2] = {b0, b1}, bvB[2] = {b2, b3};
                    mma_f16(oacc[2 * pair],     pfrag[ks], bvA);
                    mma_f16(oacc[2 * pair + 1], pfrag[ks], bvB);
                }
            }
        }
    }

    float d0 = dp0;
    d0 += __shfl_xor_sync(0xFFFFFFFFu, d0, 1);
    d0 += __shfl_xor_sync(0xFFFFFFFFu, d0, 2);
    float d1 = dp1;
    d1 += __shfl_xor_sync(0xFFFFFFFFu, d1, 1);
    d1 += __shfl_xor_sync(0xFFFFFFFFu, d1, 2);
    float inv0 = __fdividef(1.f, d0 + EPS);
    float inv1 = __fdividef(1.f, d1 + EPS);

    __half* Ag = g_A + ((size_t)b * SEQ + qt * AQT) * HID + h * HDIM;
    int row0 = wq + g, row1 = wq + g + 8;
#pragma unroll
    for (int nf = 0; nf < 8; ++nf) {
        int c0 = nf * 8 + 2 * tk;
        *(uint32_t*)&Ag[(size_t)row0 * HID + c0] =
            h2u(__floats2half2_rn(oacc[nf][0] * inv0, oacc[nf][1] * inv0));
        *(uint32_t*)&Ag[(size_t)row1 * HID + c0] =
            h2u(__floats2half2_rn(oacc[nf][2] * inv1, oacc[nf][3] * inv1));
    }
}

// ---------------------------------------------------------------------------
extern "C" void kernel_launch(void* const* d_in, const int* in_sizes, int n_in,
                              void* d_out, int out_size)
{
    __half *QKVp, *Ap, *Xp, *Wp;
    cudaGetSymbolAddress((void**)&QKVp, g_QKV);
    cudaGetSymbolAddress((void**)&Ap, g_A);
    cudaGetSymbolAddress((void**)&Xp, g_X);
    cudaGetSymbolAddress((void**)&Wp, g_W);

    cudaFuncSetAttribute(attn_f16, cudaFuncAttributeMaxDynamicSharedMemorySize, ASM_TOTAL);
    cudaFuncSetAttribute(gemm_f16<true>,  cudaFuncAttributeMaxDynamicSharedMemorySize, G_SMEM);
    cudaFuncSetAttribute(gemm_f16<false>, cudaFuncAttributeMaxDynamicSharedMemorySize, G_SMEM);

    const float* x  = (const float*)d_in[0];
    const float* Wq = (const float*)d_in[1];
    const float* Wk = (const float*)d_in[2];
    const float* Wv = (const float*)d_in[3];
    const float* Wo = (const float*)d_in[4];
    float* out = (float*)d_out;

    to_half_all<<<512, 256>>>((const float4*)x,
                              (const float4*)Wq, (const float4*)Wk,
                              (const float4*)Wv, (const float4*)Wo,
                              (uint2*)Xp, (uint2*)Wp);

    dim3 qkvGrid(STR3 / 128, MTOT / 128);  // (24, 32)
    gemm_f16<true><<<qkvGrid, 256, G_SMEM>>>(Xp, Wp, QKVp, MTOT, STR3, HID);

    dim3 attnGrid(SEQ / AQT, NHEAD, Bsz);  // (8, 16, 2)
    attn_f16<<<attnGrid, 512, ASM_TOTAL>>>();

    dim3 oGrid(HID / 128, MTOT / 128);     // (8, 32)
    gemm_f16<false><<<oGrid, 256, G_SMEM>>>(Ap, Wp + 3 * HID * HID, out, MTOT, HID, HID);
}